// round 12
// baseline (speedup 1.0000x reference)
#include <cstdint>
#include <stdint.h>
#include <cuda_runtime.h>
#include <cuda_bf16.h>
#include <mma.h>
#include <math.h>

using namespace nvcuda;

#define BSZ   16
#define TT    16
#define QQ    100
#define HIDD  256
#define PROJD 256
#define NI    1600    // BS*Q
#define MROWS 25600   // BS*T*Q
#define NNEG  3200
#define NJB   (NNEG / 64)      // 50 j-blocks of 64
#define MAXC  (NI / 64 + TT)   // 41 chunk slots upper bound

// -------- scratch (device globals; no allocation allowed) --------
__device__ __nv_bfloat16 g_neg_h[NNEG * TT * PROJD];
__device__ __nv_bfloat16 g_neg_l[NNEG * TT * PROJD];
__device__ float g_nsq[NNEG * TT];
__device__ __nv_bfloat16 g_a_h[NI * PROJD];
__device__ __nv_bfloat16 g_a_l[NI * PROJD];
__device__ float g_asq[NI];
__device__ float g_numer[NI];
__device__ float g_inv2s[NI];
__device__ float g_part[NI * 256];
__device__ float g_self[NI];
__device__ float g_brown[NI];
__device__ float g_ht[NI];
__device__ __nv_bfloat16 g_wt_hi[PROJD * HIDD];
__device__ __nv_bfloat16 g_wt_lo[PROJD * HIDD];
__device__ int g_bucket_cnt[TT];
__device__ int g_bitems[TT * NI];

__device__ __forceinline__ float warp_sum(float v) {
    #pragma unroll
    for (int o = 16; o > 0; o >>= 1) v += __shfl_xor_sync(0xffffffffu, v, o);
    return v;
}

__device__ __forceinline__ uint32_t smem_u32(const void* p) {
    uint32_t a;
    asm("{ .reg .u64 t; cvta.to.shared.u64 t, %1; cvt.u32.u64 %0, t; }" : "=r"(a) : "l"(p));
    return a;
}
__device__ __forceinline__ void cp16(uint32_t dst, const void* src) {
    asm volatile("cp.async.cg.shared.global [%0], [%1], 16;" :: "r"(dst), "l"(src));
}
#define CP_COMMIT() asm volatile("cp.async.commit_group;" ::: "memory")
#define CP_WAIT0()  asm volatile("cp.async.wait_group 0;" ::: "memory")
#define CP_WAIT1()  asm volatile("cp.async.wait_group 1;" ::: "memory")

__device__ __forceinline__ void ld_rec4(const __nv_bfloat16* __restrict__ h,
                                        const __nv_bfloat16* __restrict__ l,
                                        size_t idx, float* out) {
    __nv_bfloat162 h0 = *(const __nv_bfloat162*)&h[idx];
    __nv_bfloat162 h1 = *(const __nv_bfloat162*)&h[idx + 2];
    __nv_bfloat162 l0 = *(const __nv_bfloat162*)&l[idx];
    __nv_bfloat162 l1 = *(const __nv_bfloat162*)&l[idx + 2];
    out[0] = __bfloat162float(h0.x) + __bfloat162float(l0.x);
    out[1] = __bfloat162float(h0.y) + __bfloat162float(l0.y);
    out[2] = __bfloat162float(h1.x) + __bfloat162float(l1.x);
    out[3] = __bfloat162float(h1.y) + __bfloat162float(l1.y);
}

// sorted-desc top-5 insert
__device__ __forceinline__ void ins5(float* t5, float v) {
    if (v > t5[4]) {
        if (v > t5[0])      { t5[4]=t5[3]; t5[3]=t5[2]; t5[2]=t5[1]; t5[1]=t5[0]; t5[0]=v; }
        else if (v > t5[1]) { t5[4]=t5[3]; t5[3]=t5[2]; t5[2]=t5[1]; t5[1]=v; }
        else if (v > t5[2]) { t5[4]=t5[3]; t5[3]=t5[2]; t5[2]=v; }
        else if (v > t5[3]) { t5[4]=t5[3]; t5[3]=v; }
        else                { t5[4]=v; }
    }
}

// ============ Kernel 0: W -> W^T split into bf16 hi/lo ============
__global__ void __launch_bounds__(256) convert_w_kernel(const float* __restrict__ W)
{
    if (blockIdx.x == 0 && threadIdx.x < TT) g_bucket_cnt[threadIdx.x] = 0;
    int k = blockIdx.x;
    int n = threadIdx.x;
    float v = W[k * PROJD + n];
    __nv_bfloat16 h = __float2bfloat16(v);
    g_wt_hi[n * HIDD + k] = h;
    g_wt_lo[n * HIDD + k] = __float2bfloat16(v - __bfloat162float(h));
}

// ============ Kernel 1: fully pipelined wmma projection (64M x 256N per CTA) ============
// B hi/lo double-buffered cp.async; A chunk register-prefetched. 1 CTA/SM.
#define KC   64
#define LDA  72
#define LDB  72
#define STG_LD 260

#define OFF_BIAS  0
#define OFF_A_HI  1024
#define OFF_A_LO  (OFF_A_HI + 64 * LDA * 2)      // 10240
#define OFF_B0H   (OFF_A_LO + 64 * LDA * 2)      // 19456
#define OFF_B0L   (OFF_B0H + 256 * LDB * 2)      // 56320
#define OFF_B1H   (OFF_B0L + 256 * LDB * 2)      // 93184
#define OFF_B1L   (OFF_B1H + 256 * LDB * 2)      // 130048
#define PROJ_SMEM (OFF_B1L + 256 * LDB * 2)      // 166912
#define OFF_U     1024                           // stage-out overlays A+B0 after MMAs

__global__ void __launch_bounds__(256, 1) proj_mma_kernel(
    const float* __restrict__ fe, const float* __restrict__ ofe,
    const float* __restrict__ bias)
{
    extern __shared__ char smem_raw[];
    uint32_t sb = smem_u32(smem_raw);
    float* bias_s = (float*)(smem_raw + OFF_BIAS);
    __nv_bfloat16* Ah = (__nv_bfloat16*)(smem_raw + OFF_A_HI);
    __nv_bfloat16* Al = (__nv_bfloat16*)(smem_raw + OFF_A_LO);
    float* stage = (float*)(smem_raw + OFF_U);

    int tid  = threadIdx.x;
    int wid  = tid >> 5;
    int lane = tid & 31;

    int b = blockIdx.x;
    const float* A = (b < 400) ? fe : ofe;
    int base = (b < 400) ? 0 : NI;
    int m0   = (b % 400) * 64;

    bias_s[tid] = bias[tid];

    int wm = wid >> 2;
    int wn = wid & 3;

    // A load indexing (constant across chunks)
    int a_row = tid >> 4;       // with it in 0..3: rows a_row, +16, +32, +48... actually flat>>4
    // keep original mapping: flat = it*256+tid; row = flat>>4; j = flat&15

    wmma::fragment<wmma::accumulator, 16, 16, 16, float> acc[2][4];
    #pragma unroll
    for (int mt = 0; mt < 2; mt++)
        #pragma unroll
        for (int nt = 0; nt < 4; nt++)
            wmma::fill_fragment(acc[mt][nt], 0.0f);

    // issue B chunk c into buffer buf (hi+lo), 16 cp16 per thread
    auto issueB = [&](int c, int offH, int offL) {
        int k0 = c * KC;
        #pragma unroll
        for (int it = 0; it < 8; it++) {
            int flat = it * 256 + tid;
            int n = flat >> 3;
            int u = flat & 7;
            cp16(sb + offH + n * (LDB * 2) + u * 16, &g_wt_hi[(size_t)n * HIDD + k0 + u * 8]);
            cp16(sb + offL + n * (LDB * 2) + u * 16, &g_wt_lo[(size_t)n * HIDD + k0 + u * 8]);
        }
    };

    // ---- prologue: A chunk 0 -> regs; B chunk 0 -> buf0 ----
    float4 areg[4];
    #pragma unroll
    for (int it = 0; it < 4; it++) {
        int flat = it * 256 + tid;
        int row  = flat >> 4;
        int j    = flat & 15;
        areg[it] = *(const float4*)&A[(size_t)(m0 + row) * HIDD + 0 + j * 4];
    }
    issueB(0, OFF_B0H, OFF_B0L);
    CP_COMMIT();

    #pragma unroll
    for (int c = 0; c < 4; c++) {
        __syncthreads();   // prior MMA finished reading Ah/Al
        // ---- convert A regs -> smem hi/lo ----
        #pragma unroll
        for (int it = 0; it < 4; it++) {
            int flat = it * 256 + tid;
            int row  = flat >> 4;
            int j    = flat & 15;
            float4 v = areg[it];
            __nv_bfloat16 h0 = __float2bfloat16(v.x);
            __nv_bfloat16 h1 = __float2bfloat16(v.y);
            __nv_bfloat16 h2 = __float2bfloat16(v.z);
            __nv_bfloat16 h3 = __float2bfloat16(v.w);
            __nv_bfloat16 l0 = __float2bfloat16(v.x - __bfloat162float(h0));
            __nv_bfloat16 l1 = __float2bfloat16(v.y - __bfloat162float(h1));
            __nv_bfloat16 l2 = __float2bfloat16(v.z - __bfloat162float(h2));
            __nv_bfloat16 l3 = __float2bfloat16(v.w - __bfloat162float(h3));
            int o = row * LDA + j * 4;
            *(__nv_bfloat162*)&Ah[o]     = __nv_bfloat162{h0, h1};
            *(__nv_bfloat162*)&Ah[o + 2] = __nv_bfloat162{h2, h3};
            *(__nv_bfloat162*)&Al[o]     = __nv_bfloat162{l0, l1};
            *(__nv_bfloat162*)&Al[o + 2] = __nv_bfloat162{l2, l3};
        }
        if (c < 3) {
            // ---- prefetch A chunk c+1 into regs (consumed next iter) ----
            int k0n = (c + 1) * KC;
            #pragma unroll
            for (int it = 0; it < 4; it++) {
                int flat = it * 256 + tid;
                int row  = flat >> 4;
                int j    = flat & 15;
                areg[it] = *(const float4*)&A[(size_t)(m0 + row) * HIDD + k0n + j * 4];
            }
            // ---- issue B chunk c+1 into other buffer ----
            if ((c + 1) & 1) issueB(c + 1, OFF_B1H, OFF_B1L);
            else             issueB(c + 1, OFF_B0H, OFF_B0L);
            CP_COMMIT();
            CP_WAIT1();     // B chunk c complete
        } else {
            CP_WAIT0();
        }
        __syncthreads();

        const __nv_bfloat16* Bh = (const __nv_bfloat16*)(smem_raw + ((c & 1) ? OFF_B1H : OFF_B0H));
        const __nv_bfloat16* Bl = (const __nv_bfloat16*)(smem_raw + ((c & 1) ? OFF_B1L : OFF_B0L));

        #pragma unroll
        for (int kt = 0; kt < KC / 16; kt++) {
            wmma::fragment<wmma::matrix_a, 16, 16, 16, __nv_bfloat16, wmma::row_major> ah[2], al[2];
            #pragma unroll
            for (int mt = 0; mt < 2; mt++) {
                int row0 = wm * 32 + mt * 16;
                wmma::load_matrix_sync(ah[mt], Ah + row0 * LDA + kt * 16, LDA);
                wmma::load_matrix_sync(al[mt], Al + row0 * LDA + kt * 16, LDA);
            }
            #pragma unroll
            for (int nt = 0; nt < 4; nt++) {
                int n0 = wn * 64 + nt * 16;
                wmma::fragment<wmma::matrix_b, 16, 16, 16, __nv_bfloat16, wmma::col_major> bh, bl;
                wmma::load_matrix_sync(bh, Bh + n0 * LDB + kt * 16, LDB);
                wmma::load_matrix_sync(bl, Bl + n0 * LDB + kt * 16, LDB);
                #pragma unroll
                for (int mt = 0; mt < 2; mt++) {
                    wmma::mma_sync(acc[mt][nt], ah[mt], bh, acc[mt][nt]);
                    wmma::mma_sync(acc[mt][nt], al[mt], bh, acc[mt][nt]);
                    wmma::mma_sync(acc[mt][nt], ah[mt], bl, acc[mt][nt]);
                }
            }
        }
    }

    __syncthreads();
    #pragma unroll
    for (int mt = 0; mt < 2; mt++) {
        int row0 = wm * 32 + mt * 16;
        #pragma unroll
        for (int nt = 0; nt < 4; nt++) {
            int n0 = wn * 64 + nt * 16;
            wmma::store_matrix_sync(stage + row0 * STG_LD + n0, acc[mt][nt],
                                    STG_LD, wmma::mem_row_major);
        }
    }
    __syncthreads();

    for (int rr = 0; rr < 8; rr++) {
        int r = wid * 8 + rr;
        float v[8];
        float ss = 0.0f;
        #pragma unroll
        for (int u = 0; u < 8; u++) {
            int cidx = lane + 32 * u;
            float x = stage[r * STG_LD + cidx] + bias_s[cidx];
            v[u] = x;
            ss += x * x;
        }
        ss = warp_sum(ss);
        float inv = rsqrtf(ss);
        int m = m0 + r;
        int q = m % QQ;
        int t = (m / QQ) % TT;
        int bs = m / (QQ * TT);
        int orow = (base + bs * QQ + q) * TT + t;
        #pragma unroll
        for (int u = 0; u < 8; u++) {
            float x = v[u] * inv;
            __nv_bfloat16 h = __float2bfloat16(x);
            size_t o = (size_t)orow * PROJD + lane + 32 * u;
            g_neg_h[o] = h;
            g_neg_l[o] = __float2bfloat16(x - __bfloat162float(h));
        }
        if (lane == 0) g_nsq[orow] = ss * inv * inv;
    }
}

// ============ Kernel 2: bridge prep + fused head-tail + bucket push ============
__global__ void __launch_bounds__(256) bridge_prep_kernel(const int* __restrict__ bridge)
{
    int warp = threadIdx.x >> 5;
    int lane = threadIdx.x & 31;
    int i = blockIdx.x * 8 + warp;
    int bh = bridge[i * 3 + 0];
    int bp = bridge[i * 3 + 1];
    int bt = bridge[i * 3 + 2];
    float bhf = (float)bh, bpf = (float)bp, btf = (float)bt;
    float alpha = (bpf - bhf) / (btf - bhf);
    float sigma = alpha * (btf - bpf);
    float inv2s = 1.0f / (2.0f * sigma * sigma);

    size_t r0 = (size_t)(i * TT + bh) * PROJD;
    size_t r1 = (size_t)(i * TT + bp) * PROJD;
    size_t r2 = (size_t)(i * TT + bt) * PROJD;
    size_t rh = (size_t)(i * TT + 0) * PROJD;
    size_t rt = (size_t)(i * TT + (TT - 1)) * PROJD;
    float oma = 1.0f - alpha;
    float xs = 0.0f, as = 0.0f, ht = 0.0f;
    #pragma unroll
    for (int h = 0; h < 2; h++) {
        int c = h * 128 + lane * 4;
        float g0[4], g1[4], g2[4], gh[4], gt[4];
        ld_rec4(g_neg_h, g_neg_l, r0 + c, g0);
        ld_rec4(g_neg_h, g_neg_l, r1 + c, g1);
        ld_rec4(g_neg_h, g_neg_l, r2 + c, g2);
        ld_rec4(g_neg_h, g_neg_l, rh + c, gh);
        ld_rec4(g_neg_h, g_neg_l, rt + c, gt);
        #pragma unroll
        for (int e = 0; e < 4; e++) {
            float aa = oma * g0[e] + alpha * g2[e];
            float x  = g1[e] - oma * g0[e] - alpha * g2[e];
            xs += x * x;
            as += aa * aa;
            ht += gh[e] * gt[e];
            __nv_bfloat16 ahv = __float2bfloat16(aa);
            size_t o = (size_t)i * PROJD + c + e;
            g_a_h[o] = ahv;
            g_a_l[o] = __float2bfloat16(aa - __bfloat162float(ahv));
        }
    }
    xs = warp_sum(xs);
    as = warp_sum(as);
    ht = warp_sum(ht);
    if (lane == 0) {
        g_inv2s[i] = inv2s;
        g_asq[i]   = as;
        g_numer[i] = expf(-xs * inv2s);
        float z = 0.3f - ht;
        g_ht[i] = log1pf(expf(z));
        int pos = atomicAdd(&g_bucket_cnt[bp], 1);
        g_bitems[bp * NI + pos] = i;
    }
}

// ============ Kernel 3: dist GEMM — 64i x 64j per CTA, 3 CTAs/SM, cp.async pipeline ============
#define DKC   64
#define DLD3  72
#define DSTG3 72
#define DS_AH   0
#define DS_AL   9216
#define DS_BH   18432
#define DS_BL   27648
#define DS_SZ   36864
#define D3_IDX  (2 * DS_SZ)
#define DIST_SMEM (D3_IDX + 64 * 4 + 16)

__global__ void __launch_bounds__(256, 3) dist_mma_kernel()
{
    extern __shared__ char smem_raw[];
    uint32_t sbase = smem_u32(smem_raw);
    float* stage = (float*)(smem_raw);
    int* sitems = (int*)(smem_raw + D3_IDX);

    int cidx = blockIdx.y;
    int t = -1, off = 0;
    {
        int acc_c = 0;
        #pragma unroll
        for (int tt2 = 0; tt2 < TT; tt2++) {
            int nch = (g_bucket_cnt[tt2] + 63) >> 6;
            if (t < 0 && cidx < acc_c + nch) { t = tt2; off = (cidx - acc_c) * 64; }
            acc_c += nch;
        }
    }
    if (t < 0) return;
    int cc = min(64, g_bucket_cnt[t] - off);
    int jblock = blockIdx.x;
    int j0 = jblock * 64;

    int tid = threadIdx.x;
    int wid = tid >> 5;
    int wm = wid >> 2;
    int wn = wid & 3;

    if (tid < 64)
        sitems[tid] = g_bitems[t * NI + off + ((tid < cc) ? tid : 0)];
    __syncthreads();

    int l_r0 = tid >> 3;
    int l_k  = tid & 7;
    int ai0 = sitems[l_r0];
    int ai1 = sitems[32 + l_r0];

    wmma::fragment<wmma::accumulator, 16, 16, 16, float> acc[2];
    wmma::fill_fragment(acc[0], 0.0f);
    wmma::fill_fragment(acc[1], 0.0f);

    auto prefetch = [&](int c, int buf) {
        int kbase = c * DKC;
        uint32_t st = sbase + buf * DS_SZ;
        uint32_t d0 = st + l_r0 * 144 + l_k * 16;
        uint32_t d1 = st + (32 + l_r0) * 144 + l_k * 16;
        size_t sa0 = (size_t)ai0 * PROJD + kbase + l_k * 8;
        size_t sa1 = (size_t)ai1 * PROJD + kbase + l_k * 8;
        cp16(d0 + DS_AH, &g_a_h[sa0]);
        cp16(d1 + DS_AH, &g_a_h[sa1]);
        cp16(d0 + DS_AL, &g_a_l[sa0]);
        cp16(d1 + DS_AL, &g_a_l[sa1]);
        size_t sb0 = (size_t)((j0 + l_r0) * TT + t) * PROJD + kbase + l_k * 8;
        size_t sb1 = (size_t)((j0 + 32 + l_r0) * TT + t) * PROJD + kbase + l_k * 8;
        cp16(d0 + DS_BH, &g_neg_h[sb0]);
        cp16(d1 + DS_BH, &g_neg_h[sb1]);
        cp16(d0 + DS_BL, &g_neg_l[sb0]);
        cp16(d1 + DS_BL, &g_neg_l[sb1]);
    };

    prefetch(0, 0);
    CP_COMMIT();

    #pragma unroll
    for (int c = 0; c < 4; c++) {
        int buf = c & 1;
        if (c < 3) { prefetch(c + 1, (c + 1) & 1); CP_COMMIT(); CP_WAIT1(); }
        else       { CP_WAIT0(); }
        __syncthreads();

        const __nv_bfloat16* Ah = (const __nv_bfloat16*)(smem_raw + buf * DS_SZ + DS_AH);
        const __nv_bfloat16* Al = (const __nv_bfloat16*)(smem_raw + buf * DS_SZ + DS_AL);
        const __nv_bfloat16* Bh = (const __nv_bfloat16*)(smem_raw + buf * DS_SZ + DS_BH);
        const __nv_bfloat16* Bl = (const __nv_bfloat16*)(smem_raw + buf * DS_SZ + DS_BL);

        #pragma unroll
        for (int kt = 0; kt < DKC / 16; kt++) {
            wmma::fragment<wmma::matrix_a, 16, 16, 16, __nv_bfloat16, wmma::row_major> ah[2], al[2];
            #pragma unroll
            for (int mt = 0; mt < 2; mt++) {
                int row0 = wm * 32 + mt * 16;
                wmma::load_matrix_sync(ah[mt], Ah + row0 * DLD3 + kt * 16, DLD3);
                wmma::load_matrix_sync(al[mt], Al + row0 * DLD3 + kt * 16, DLD3);
            }
            wmma::fragment<wmma::matrix_b, 16, 16, 16, __nv_bfloat16, wmma::col_major> bh, bl;
            wmma::load_matrix_sync(bh, Bh + (wn * 16) * DLD3 + kt * 16, DLD3);
            wmma::load_matrix_sync(bl, Bl + (wn * 16) * DLD3 + kt * 16, DLD3);
            #pragma unroll
            for (int mt = 0; mt < 2; mt++) {
                wmma::mma_sync(acc[mt], ah[mt], bh, acc[mt]);
                wmma::mma_sync(acc[mt], al[mt], bh, acc[mt]);
                wmma::mma_sync(acc[mt], ah[mt], bl, acc[mt]);
            }
        }
        __syncthreads();
    }

    #pragma unroll
    for (int mt = 0; mt < 2; mt++)
        wmma::store_matrix_sync(stage + (wm * 32 + mt * 16) * DSTG3 + wn * 16,
                                acc[mt], DSTG3, wmma::mem_row_major);
    __syncthreads();

    int r  = tid >> 2;
    int c0 = (tid & 3) * 16;
    int i = sitems[r];
    bool valid = (r < cc);
    float asqi = g_asq[i];
    float is2  = g_inv2s[i];
    float t5[5] = {-1e30f, -1e30f, -1e30f, -1e30f, -1e30f};
    #pragma unroll
    for (int u = 0; u < 16; u++) {
        int j = j0 + c0 + u;
        float cross = stage[r * DSTG3 + c0 + u];
        float d = -(g_nsq[j * TT + t] - 2.0f * cross + asqi) * is2;
        if (j == i) { if (valid) g_self[i] = d; d = -10000.0f; }
        ins5(t5, d);
    }
    #pragma unroll
    for (int o2 = 1; o2 <= 2; o2 <<= 1) {
        float b0 = __shfl_xor_sync(0xffffffffu, t5[0], o2);
        float b1 = __shfl_xor_sync(0xffffffffu, t5[1], o2);
        float b2 = __shfl_xor_sync(0xffffffffu, t5[2], o2);
        float b3 = __shfl_xor_sync(0xffffffffu, t5[3], o2);
        float b4 = __shfl_xor_sync(0xffffffffu, t5[4], o2);
        ins5(t5, b0); ins5(t5, b1); ins5(t5, b2); ins5(t5, b3); ins5(t5, b4);
    }
    if (valid && (tid & 3) == 0) {
        float* dst = &g_part[(size_t)i * 256 + jblock * 5];
        dst[0] = t5[0]; dst[1] = t5[1]; dst[2] = t5[2]; dst[3] = t5[3]; dst[4] = t5[4];
    }
}

// ============ Kernel 4: warp-per-row merge of partial top-5s ============
__global__ void __launch_bounds__(256) topk_kernel()
{
    int wid  = threadIdx.x >> 5;
    int lane = threadIdx.x & 31;
    int i = blockIdx.x * 8 + wid;
    const float* part = &g_part[(size_t)i * 256];

    float t5[5] = {-1e30f, -1e30f, -1e30f, -1e30f, -1e30f};
    for (int k = lane; k < NJB * 5; k += 32) ins5(t5, part[k]);
    #pragma unroll
    for (int off = 16; off > 0; off >>= 1) {
        float b0 = __shfl_xor_sync(0xffffffffu, t5[0], off);
        float b1 = __shfl_xor_sync(0xffffffffu, t5[1], off);
        float b2 = __shfl_xor_sync(0xffffffffu, t5[2], off);
        float b3 = __shfl_xor_sync(0xffffffffu, t5[3], off);
        float b4 = __shfl_xor_sync(0xffffffffu, t5[4], off);
        ins5(t5, b0); ins5(t5, b1); ins5(t5, b2); ins5(t5, b3); ins5(t5, b4);
    }
    if (lane == 0) {
        float deno = expf(g_self[i]);
        #pragma unroll
        for (int k = 0; k < 5; k++) deno += expf(t5[k]);
        g_brown[i] = g_numer[i] / deno;
    }
}

// ============ Kernel 5: deterministic final reduction ============
__global__ void __launch_bounds__(256) final_kernel(float* __restrict__ out)
{
    __shared__ float sb[256], sh[256];
    int tid = threadIdx.x;
    float b = 0.0f, h = 0.0f;
    for (int i = tid; i < NI; i += 256) { b += g_brown[i]; h += g_ht[i]; }
    sb[tid] = b; sh[tid] = h;
    __syncthreads();
    for (int s = 128; s > 0; s >>= 1) {
        if (tid < s) { sb[tid] += sb[tid + s]; sh[tid] += sh[tid + s]; }
        __syncthreads();
    }
    if (tid == 0) {
        out[0] = sb[0] / (float)NI;
        out[1] = sh[0] / (float)NI;
    }
}

// ==================== launch ====================
extern "C" void kernel_launch(void* const* d_in, const int* in_sizes, int n_in,
                              void* d_out, int out_size)
{
    const float* fe     = (const float*)d_in[0];
    const float* ofe    = (const float*)d_in[1];
    const float* W      = (const float*)d_in[2];
    const float* bias   = (const float*)d_in[3];
    const int*   bridge = (const int*)d_in[4];
    float* out = (float*)d_out;

    cudaFuncSetAttribute(proj_mma_kernel, cudaFuncAttributeMaxDynamicSharedMemorySize, PROJ_SMEM);
    cudaFuncSetAttribute(dist_mma_kernel, cudaFuncAttributeMaxDynamicSharedMemorySize, DIST_SMEM);

    convert_w_kernel<<<HIDD, PROJD>>>(W);
    proj_mma_kernel<<<800, 256, PROJ_SMEM>>>(fe, ofe, bias);

    bridge_prep_kernel<<<NI / 8, 256>>>(bridge);
    dist_mma_kernel<<<dim3(NJB, MAXC), 256, DIST_SMEM>>>();
    topk_kernel<<<NI / 8, 256>>>();
    final_kernel<<<1, 256>>>(out);
}

// round 13
// speedup vs baseline: 1.1586x; 1.1586x over previous
#include <cstdint>
#include <stdint.h>
#include <cuda_runtime.h>
#include <cuda_bf16.h>
#include <mma.h>
#include <math.h>

using namespace nvcuda;

#define BSZ   16
#define TT    16
#define QQ    100
#define HIDD  256
#define PROJD 256
#define NI    1600    // BS*Q
#define MROWS 25600   // BS*T*Q
#define NNEG  3200
#define NJB   (NNEG / 64)      // 50 j-blocks of 64
#define MAXC  (NI / 64 + TT)   // 41 chunk slots upper bound

// -------- scratch (device globals; no allocation allowed) --------
__device__ __nv_bfloat16 g_neg_h[NNEG * TT * PROJD];
__device__ __nv_bfloat16 g_neg_l[NNEG * TT * PROJD];
__device__ float g_nsq[NNEG * TT];
__device__ __nv_bfloat16 g_a_h[NI * PROJD];
__device__ __nv_bfloat16 g_a_l[NI * PROJD];
__device__ float g_asq[NI];
__device__ float g_numer[NI];
__device__ float g_inv2s[NI];
__device__ float g_part[NI * 256];
__device__ float g_self[NI];
__device__ float g_brown[NI];
__device__ float g_ht[NI];
__device__ __nv_bfloat16 g_wt_hi[PROJD * HIDD];
__device__ __nv_bfloat16 g_wt_lo[PROJD * HIDD];
__device__ int g_bucket_cnt[TT];
__device__ int g_bitems[TT * NI];

__device__ __forceinline__ float warp_sum(float v) {
    #pragma unroll
    for (int o = 16; o > 0; o >>= 1) v += __shfl_xor_sync(0xffffffffu, v, o);
    return v;
}

__device__ __forceinline__ uint32_t smem_u32(const void* p) {
    uint32_t a;
    asm("{ .reg .u64 t; cvta.to.shared.u64 t, %1; cvt.u32.u64 %0, t; }" : "=r"(a) : "l"(p));
    return a;
}
__device__ __forceinline__ void cp16(uint32_t dst, const void* src) {
    asm volatile("cp.async.cg.shared.global [%0], [%1], 16;" :: "r"(dst), "l"(src));
}
#define CP_COMMIT() asm volatile("cp.async.commit_group;" ::: "memory")
#define CP_WAIT0()  asm volatile("cp.async.wait_group 0;" ::: "memory")
#define CP_WAIT1()  asm volatile("cp.async.wait_group 1;" ::: "memory")

__device__ __forceinline__ void ld_rec4(const __nv_bfloat16* __restrict__ h,
                                        const __nv_bfloat16* __restrict__ l,
                                        size_t idx, float* out) {
    __nv_bfloat162 h0 = *(const __nv_bfloat162*)&h[idx];
    __nv_bfloat162 h1 = *(const __nv_bfloat162*)&h[idx + 2];
    __nv_bfloat162 l0 = *(const __nv_bfloat162*)&l[idx];
    __nv_bfloat162 l1 = *(const __nv_bfloat162*)&l[idx + 2];
    out[0] = __bfloat162float(h0.x) + __bfloat162float(l0.x);
    out[1] = __bfloat162float(h0.y) + __bfloat162float(l0.y);
    out[2] = __bfloat162float(h1.x) + __bfloat162float(l1.x);
    out[3] = __bfloat162float(h1.y) + __bfloat162float(l1.y);
}

// sorted-desc top-5 insert
__device__ __forceinline__ void ins5(float* t5, float v) {
    if (v > t5[4]) {
        if (v > t5[0])      { t5[4]=t5[3]; t5[3]=t5[2]; t5[2]=t5[1]; t5[1]=t5[0]; t5[0]=v; }
        else if (v > t5[1]) { t5[4]=t5[3]; t5[3]=t5[2]; t5[2]=t5[1]; t5[1]=v; }
        else if (v > t5[2]) { t5[4]=t5[3]; t5[3]=t5[2]; t5[2]=v; }
        else if (v > t5[3]) { t5[4]=t5[3]; t5[3]=v; }
        else                { t5[4]=v; }
    }
}

// ============ Kernel 0: W -> W^T split into bf16 hi/lo ============
__global__ void __launch_bounds__(256) convert_w_kernel(const float* __restrict__ W)
{
    if (blockIdx.x == 0 && threadIdx.x < TT) g_bucket_cnt[threadIdx.x] = 0;
    int k = blockIdx.x;
    int n = threadIdx.x;
    float v = W[k * PROJD + n];
    __nv_bfloat16 h = __float2bfloat16(v);
    g_wt_hi[n * HIDD + k] = h;
    g_wt_lo[n * HIDD + k] = __float2bfloat16(v - __bfloat162float(h));
}

// ============ Kernel 1: wmma bf16-split projection (64M x 256N per CTA, 2 CTA/SM) ============
#define KC   64
#define LDA  72
#define LDB  72
#define STG_LD 260

#define OFF_BIAS  0
#define OFF_U     1024
#define OFF_A_HI  (OFF_U)
#define OFF_A_LO  (OFF_A_HI + 64 * LDA * 2)
#define OFF_B_HI  (OFF_A_LO + 64 * LDA * 2)
#define OFF_B_LO  (OFF_B_HI + 256 * LDB * 2)
#define TILES_END (OFF_B_LO + 256 * LDB * 2)
#define STG_END   (OFF_U + 64 * STG_LD * 4)
#define PROJ_SMEM (STG_END > TILES_END ? STG_END : TILES_END)

__global__ void __launch_bounds__(256, 2) proj_mma_kernel(
    const float* __restrict__ fe, const float* __restrict__ ofe,
    const float* __restrict__ bias)
{
    extern __shared__ char smem_raw[];
    uint32_t sb = smem_u32(smem_raw);
    float* bias_s = (float*)(smem_raw + OFF_BIAS);
    __nv_bfloat16* Ah = (__nv_bfloat16*)(smem_raw + OFF_A_HI);
    __nv_bfloat16* Al = (__nv_bfloat16*)(smem_raw + OFF_A_LO);
    __nv_bfloat16* Bh = (__nv_bfloat16*)(smem_raw + OFF_B_HI);
    __nv_bfloat16* Bl = (__nv_bfloat16*)(smem_raw + OFF_B_LO);
    float* stage = (float*)(smem_raw + OFF_U);

    int tid  = threadIdx.x;
    int wid  = tid >> 5;
    int lane = tid & 31;

    int b = blockIdx.x;
    const float* A = (b < 400) ? fe : ofe;
    int base = (b < 400) ? 0 : NI;
    int m0   = (b % 400) * 64;

    bias_s[tid] = bias[tid];

    int wm = wid >> 2;
    int wn = wid & 3;

    wmma::fragment<wmma::accumulator, 16, 16, 16, float> acc[2][4];
    #pragma unroll
    for (int mt = 0; mt < 2; mt++)
        #pragma unroll
        for (int nt = 0; nt < 4; nt++)
            wmma::fill_fragment(acc[mt][nt], 0.0f);

    for (int c = 0; c < 4; c++) {
        int k0 = c * KC;
        __syncthreads();
        // ---- issue B chunk via cp.async (overlaps A load/convert below) ----
        #pragma unroll
        for (int it = 0; it < 8; it++) {
            int flat = it * 256 + tid;
            int n = flat >> 3;
            int u = flat & 7;
            cp16(sb + OFF_B_HI + n * (LDB * 2) + u * 16, &g_wt_hi[(size_t)n * HIDD + k0 + u * 8]);
            cp16(sb + OFF_B_LO + n * (LDB * 2) + u * 16, &g_wt_lo[(size_t)n * HIDD + k0 + u * 8]);
        }
        CP_COMMIT();
        // ---- load & split A chunk: 64 rows x 64 fp32 ----
        #pragma unroll
        for (int it = 0; it < 4; it++) {
            int flat = it * 256 + tid;
            int row  = flat >> 4;
            int j    = flat & 15;
            float4 v = *(const float4*)&A[(size_t)(m0 + row) * HIDD + k0 + j * 4];
            __nv_bfloat16 h0 = __float2bfloat16(v.x);
            __nv_bfloat16 h1 = __float2bfloat16(v.y);
            __nv_bfloat16 h2 = __float2bfloat16(v.z);
            __nv_bfloat16 h3 = __float2bfloat16(v.w);
            __nv_bfloat16 l0 = __float2bfloat16(v.x - __bfloat162float(h0));
            __nv_bfloat16 l1 = __float2bfloat16(v.y - __bfloat162float(h1));
            __nv_bfloat16 l2 = __float2bfloat16(v.z - __bfloat162float(h2));
            __nv_bfloat16 l3 = __float2bfloat16(v.w - __bfloat162float(h3));
            int o = row * LDA + j * 4;
            *(__nv_bfloat162*)&Ah[o]     = __nv_bfloat162{h0, h1};
            *(__nv_bfloat162*)&Ah[o + 2] = __nv_bfloat162{h2, h3};
            *(__nv_bfloat162*)&Al[o]     = __nv_bfloat162{l0, l1};
            *(__nv_bfloat162*)&Al[o + 2] = __nv_bfloat162{l2, l3};
        }
        CP_WAIT0();
        __syncthreads();

        #pragma unroll
        for (int kt = 0; kt < KC / 16; kt++) {
            wmma::fragment<wmma::matrix_a, 16, 16, 16, __nv_bfloat16, wmma::row_major> ah[2], al[2];
            #pragma unroll
            for (int mt = 0; mt < 2; mt++) {
                int row0 = wm * 32 + mt * 16;
                wmma::load_matrix_sync(ah[mt], Ah + row0 * LDA + kt * 16, LDA);
                wmma::load_matrix_sync(al[mt], Al + row0 * LDA + kt * 16, LDA);
            }
            #pragma unroll
            for (int nt = 0; nt < 4; nt++) {
                int n0 = wn * 64 + nt * 16;
                wmma::fragment<wmma::matrix_b, 16, 16, 16, __nv_bfloat16, wmma::col_major> bh, bl;
                wmma::load_matrix_sync(bh, Bh + n0 * LDB + kt * 16, LDB);
                wmma::load_matrix_sync(bl, Bl + n0 * LDB + kt * 16, LDB);
                #pragma unroll
                for (int mt = 0; mt < 2; mt++) {
                    wmma::mma_sync(acc[mt][nt], ah[mt], bh, acc[mt][nt]);
                    wmma::mma_sync(acc[mt][nt], al[mt], bh, acc[mt][nt]);
                    wmma::mma_sync(acc[mt][nt], ah[mt], bl, acc[mt][nt]);
                }
            }
        }
    }

    __syncthreads();
    #pragma unroll
    for (int mt = 0; mt < 2; mt++) {
        int row0 = wm * 32 + mt * 16;
        #pragma unroll
        for (int nt = 0; nt < 4; nt++) {
            int n0 = wn * 64 + nt * 16;
            wmma::store_matrix_sync(stage + row0 * STG_LD + n0, acc[mt][nt],
                                    STG_LD, wmma::mem_row_major);
        }
    }
    __syncthreads();

    for (int rr = 0; rr < 8; rr++) {
        int r = wid * 8 + rr;
        float v[8];
        float ss = 0.0f;
        #pragma unroll
        for (int u = 0; u < 8; u++) {
            int cidx = lane + 32 * u;
            float x = stage[r * STG_LD + cidx] + bias_s[cidx];
            v[u] = x;
            ss += x * x;
        }
        ss = warp_sum(ss);
        float inv = rsqrtf(ss);
        int m = m0 + r;
        int q = m % QQ;
        int t = (m / QQ) % TT;
        int bs = m / (QQ * TT);
        int orow = (base + bs * QQ + q) * TT + t;
        #pragma unroll
        for (int u = 0; u < 8; u++) {
            float x = v[u] * inv;
            __nv_bfloat16 h = __float2bfloat16(x);
            size_t o = (size_t)orow * PROJD + lane + 32 * u;
            g_neg_h[o] = h;
            g_neg_l[o] = __float2bfloat16(x - __bfloat162float(h));
        }
        if (lane == 0) g_nsq[orow] = ss * inv * inv;
    }
}

// ============ Kernel 2: bridge prep + fused head-tail + bucket push ============
__global__ void __launch_bounds__(256) bridge_prep_kernel(const int* __restrict__ bridge)
{
    int warp = threadIdx.x >> 5;
    int lane = threadIdx.x & 31;
    int i = blockIdx.x * 8 + warp;
    int bh = bridge[i * 3 + 0];
    int bp = bridge[i * 3 + 1];
    int bt = bridge[i * 3 + 2];
    float bhf = (float)bh, bpf = (float)bp, btf = (float)bt;
    float alpha = (bpf - bhf) / (btf - bhf);
    float sigma = alpha * (btf - bpf);
    float inv2s = 1.0f / (2.0f * sigma * sigma);

    size_t r0 = (size_t)(i * TT + bh) * PROJD;
    size_t r1 = (size_t)(i * TT + bp) * PROJD;
    size_t r2 = (size_t)(i * TT + bt) * PROJD;
    size_t rh = (size_t)(i * TT + 0) * PROJD;
    size_t rt = (size_t)(i * TT + (TT - 1)) * PROJD;
    float oma = 1.0f - alpha;
    float xs = 0.0f, as = 0.0f, ht = 0.0f;
    #pragma unroll
    for (int h = 0; h < 2; h++) {
        int c = h * 128 + lane * 4;
        float g0[4], g1[4], g2[4], gh[4], gt[4];
        ld_rec4(g_neg_h, g_neg_l, r0 + c, g0);
        ld_rec4(g_neg_h, g_neg_l, r1 + c, g1);
        ld_rec4(g_neg_h, g_neg_l, r2 + c, g2);
        ld_rec4(g_neg_h, g_neg_l, rh + c, gh);
        ld_rec4(g_neg_h, g_neg_l, rt + c, gt);
        #pragma unroll
        for (int e = 0; e < 4; e++) {
            float aa = oma * g0[e] + alpha * g2[e];
            float x  = g1[e] - oma * g0[e] - alpha * g2[e];
            xs += x * x;
            as += aa * aa;
            ht += gh[e] * gt[e];
            __nv_bfloat16 ahv = __float2bfloat16(aa);
            size_t o = (size_t)i * PROJD + c + e;
            g_a_h[o] = ahv;
            g_a_l[o] = __float2bfloat16(aa - __bfloat162float(ahv));
        }
    }
    xs = warp_sum(xs);
    as = warp_sum(as);
    ht = warp_sum(ht);
    if (lane == 0) {
        g_inv2s[i] = inv2s;
        g_asq[i]   = as;
        g_numer[i] = expf(-xs * inv2s);
        float z = 0.3f - ht;
        g_ht[i] = log1pf(expf(z));
        int pos = atomicAdd(&g_bucket_cnt[bp], 1);
        g_bitems[bp * NI + pos] = i;
    }
}

// ============ Kernel 3: dist GEMM — 64i x 64j per CTA, 3 CTAs/SM, cp.async pipeline ============
#define DKC   64
#define DLD3  72
#define DSTG3 72
#define DS_AH   0
#define DS_AL   9216
#define DS_BH   18432
#define DS_BL   27648
#define DS_SZ   36864
#define D3_IDX  (2 * DS_SZ)
#define D3_NSQ  (D3_IDX + 64 * 4)
#define DIST_SMEM (D3_NSQ + 64 * 4 + 16)

__global__ void __launch_bounds__(256, 3) dist_mma_kernel()
{
    extern __shared__ char smem_raw[];
    uint32_t sbase = smem_u32(smem_raw);
    float* stage = (float*)(smem_raw);
    int* sitems = (int*)(smem_raw + D3_IDX);
    float* snsq = (float*)(smem_raw + D3_NSQ);

    int cidx = blockIdx.y;
    int t = -1, off = 0;
    {
        int acc_c = 0;
        #pragma unroll
        for (int tt2 = 0; tt2 < TT; tt2++) {
            int nch = (g_bucket_cnt[tt2] + 63) >> 6;
            if (t < 0 && cidx < acc_c + nch) { t = tt2; off = (cidx - acc_c) * 64; }
            acc_c += nch;
        }
    }
    if (t < 0) return;
    int cc = min(64, g_bucket_cnt[t] - off);
    int jblock = blockIdx.x;
    int j0 = jblock * 64;

    int tid = threadIdx.x;
    int wid = tid >> 5;
    int wm = wid >> 2;
    int wn = wid & 3;

    if (tid < 64) {
        sitems[tid] = g_bitems[t * NI + off + ((tid < cc) ? tid : 0)];
        snsq[tid]   = g_nsq[(j0 + tid) * TT + t];
    }
    __syncthreads();

    int l_r0 = tid >> 3;
    int l_k  = tid & 7;
    int ai0 = sitems[l_r0];
    int ai1 = sitems[32 + l_r0];

    wmma::fragment<wmma::accumulator, 16, 16, 16, float> acc[2];
    wmma::fill_fragment(acc[0], 0.0f);
    wmma::fill_fragment(acc[1], 0.0f);

    auto prefetch = [&](int c, int buf) {
        int kbase = c * DKC;
        uint32_t st = sbase + buf * DS_SZ;
        uint32_t d0 = st + l_r0 * 144 + l_k * 16;
        uint32_t d1 = st + (32 + l_r0) * 144 + l_k * 16;
        size_t sa0 = (size_t)ai0 * PROJD + kbase + l_k * 8;
        size_t sa1 = (size_t)ai1 * PROJD + kbase + l_k * 8;
        cp16(d0 + DS_AH, &g_a_h[sa0]);
        cp16(d1 + DS_AH, &g_a_h[sa1]);
        cp16(d0 + DS_AL, &g_a_l[sa0]);
        cp16(d1 + DS_AL, &g_a_l[sa1]);
        size_t sb0 = (size_t)((j0 + l_r0) * TT + t) * PROJD + kbase + l_k * 8;
        size_t sb1 = (size_t)((j0 + 32 + l_r0) * TT + t) * PROJD + kbase + l_k * 8;
        cp16(d0 + DS_BH, &g_neg_h[sb0]);
        cp16(d1 + DS_BH, &g_neg_h[sb1]);
        cp16(d0 + DS_BL, &g_neg_l[sb0]);
        cp16(d1 + DS_BL, &g_neg_l[sb1]);
    };

    prefetch(0, 0);
    CP_COMMIT();

    #pragma unroll
    for (int c = 0; c < 4; c++) {
        int buf = c & 1;
        if (c < 3) { prefetch(c + 1, (c + 1) & 1); CP_COMMIT(); CP_WAIT1(); }
        else       { CP_WAIT0(); }
        __syncthreads();

        const __nv_bfloat16* Ah = (const __nv_bfloat16*)(smem_raw + buf * DS_SZ + DS_AH);
        const __nv_bfloat16* Al = (const __nv_bfloat16*)(smem_raw + buf * DS_SZ + DS_AL);
        const __nv_bfloat16* Bh = (const __nv_bfloat16*)(smem_raw + buf * DS_SZ + DS_BH);
        const __nv_bfloat16* Bl = (const __nv_bfloat16*)(smem_raw + buf * DS_SZ + DS_BL);

        #pragma unroll
        for (int kt = 0; kt < DKC / 16; kt++) {
            wmma::fragment<wmma::matrix_a, 16, 16, 16, __nv_bfloat16, wmma::row_major> ah[2], al[2];
            #pragma unroll
            for (int mt = 0; mt < 2; mt++) {
                int row0 = wm * 32 + mt * 16;
                wmma::load_matrix_sync(ah[mt], Ah + row0 * DLD3 + kt * 16, DLD3);
                wmma::load_matrix_sync(al[mt], Al + row0 * DLD3 + kt * 16, DLD3);
            }
            wmma::fragment<wmma::matrix_b, 16, 16, 16, __nv_bfloat16, wmma::col_major> bh, bl;
            wmma::load_matrix_sync(bh, Bh + (wn * 16) * DLD3 + kt * 16, DLD3);
            wmma::load_matrix_sync(bl, Bl + (wn * 16) * DLD3 + kt * 16, DLD3);
            #pragma unroll
            for (int mt = 0; mt < 2; mt++) {
                wmma::mma_sync(acc[mt], ah[mt], bh, acc[mt]);
                wmma::mma_sync(acc[mt], al[mt], bh, acc[mt]);
                wmma::mma_sync(acc[mt], ah[mt], bl, acc[mt]);
            }
        }
        __syncthreads();
    }

    #pragma unroll
    for (int mt = 0; mt < 2; mt++)
        wmma::store_matrix_sync(stage + (wm * 32 + mt * 16) * DSTG3 + wn * 16,
                                acc[mt], DSTG3, wmma::mem_row_major);
    __syncthreads();

    int r  = tid >> 2;
    int c0 = (tid & 3) * 16;
    int i = sitems[r];
    bool valid = (r < cc);
    float asqi = g_asq[i];
    float is2  = g_inv2s[i];
    float t5[5] = {-1e30f, -1e30f, -1e30f, -1e30f, -1e30f};
    #pragma unroll
    for (int u = 0; u < 16; u++) {
        int j = j0 + c0 + u;
        float cross = stage[r * DSTG3 + c0 + u];
        float d = -(snsq[c0 + u] - 2.0f * cross + asqi) * is2;
        if (j == i) { if (valid) g_self[i] = d; d = -10000.0f; }
        ins5(t5, d);
    }
    #pragma unroll
    for (int o2 = 1; o2 <= 2; o2 <<= 1) {
        float b0 = __shfl_xor_sync(0xffffffffu, t5[0], o2);
        float b1 = __shfl_xor_sync(0xffffffffu, t5[1], o2);
        float b2 = __shfl_xor_sync(0xffffffffu, t5[2], o2);
        float b3 = __shfl_xor_sync(0xffffffffu, t5[3], o2);
        float b4 = __shfl_xor_sync(0xffffffffu, t5[4], o2);
        ins5(t5, b0); ins5(t5, b1); ins5(t5, b2); ins5(t5, b3); ins5(t5, b4);
    }
    if (valid && (tid & 3) == 0) {
        float* dst = &g_part[(size_t)i * 256 + jblock * 5];
        dst[0] = t5[0]; dst[1] = t5[1]; dst[2] = t5[2]; dst[3] = t5[3]; dst[4] = t5[4];
    }
}

// ============ Kernel 4: warp-per-row merge of partial top-5s ============
__global__ void __launch_bounds__(256) topk_kernel()
{
    int wid  = threadIdx.x >> 5;
    int lane = threadIdx.x & 31;
    int i = blockIdx.x * 8 + wid;
    const float* part = &g_part[(size_t)i * 256];

    float t5[5] = {-1e30f, -1e30f, -1e30f, -1e30f, -1e30f};
    for (int k = lane; k < NJB * 5; k += 32) ins5(t5, part[k]);
    #pragma unroll
    for (int off = 16; off > 0; off >>= 1) {
        float b0 = __shfl_xor_sync(0xffffffffu, t5[0], off);
        float b1 = __shfl_xor_sync(0xffffffffu, t5[1], off);
        float b2 = __shfl_xor_sync(0xffffffffu, t5[2], off);
        float b3 = __shfl_xor_sync(0xffffffffu, t5[3], off);
        float b4 = __shfl_xor_sync(0xffffffffu, t5[4], off);
        ins5(t5, b0); ins5(t5, b1); ins5(t5, b2); ins5(t5, b3); ins5(t5, b4);
    }
    if (lane == 0) {
        float deno = expf(g_self[i]);
        #pragma unroll
        for (int k = 0; k < 5; k++) deno += expf(t5[k]);
        g_brown[i] = g_numer[i] / deno;
    }
}

// ============ Kernel 5: deterministic final reduction ============
__global__ void __launch_bounds__(256) final_kernel(float* __restrict__ out)
{
    __shared__ float sb[256], sh[256];
    int tid = threadIdx.x;
    float b = 0.0f, h = 0.0f;
    for (int i = tid; i < NI; i += 256) { b += g_brown[i]; h += g_ht[i]; }
    sb[tid] = b; sh[tid] = h;
    __syncthreads();
    for (int s = 128; s > 0; s >>= 1) {
        if (tid < s) { sb[tid] += sb[tid + s]; sh[tid] += sh[tid + s]; }
        __syncthreads();
    }
    if (tid == 0) {
        out[0] = sb[0] / (float)NI;
        out[1] = sh[0] / (float)NI;
    }
}

// ==================== launch ====================
extern "C" void kernel_launch(void* const* d_in, const int* in_sizes, int n_in,
                              void* d_out, int out_size)
{
    const float* fe     = (const float*)d_in[0];
    const float* ofe    = (const float*)d_in[1];
    const float* W      = (const float*)d_in[2];
    const float* bias   = (const float*)d_in[3];
    const int*   bridge = (const int*)d_in[4];
    float* out = (float*)d_out;

    cudaFuncSetAttribute(proj_mma_kernel, cudaFuncAttributeMaxDynamicSharedMemorySize, PROJ_SMEM);
    cudaFuncSetAttribute(dist_mma_kernel, cudaFuncAttributeMaxDynamicSharedMemorySize, DIST_SMEM);

    convert_w_kernel<<<HIDD, PROJD>>>(W);
    proj_mma_kernel<<<800, 256, PROJ_SMEM>>>(fe, ofe, bias);

    bridge_prep_kernel<<<NI / 8, 256>>>(bridge);
    dist_mma_kernel<<<dim3(NJB, MAXC), 256, DIST_SMEM>>>();
    topk_kernel<<<NI / 8, 256>>>();
    final_kernel<<<1, 256>>>(out);
}

// round 14
// speedup vs baseline: 1.4012x; 1.2094x over previous
#include <cstdint>
#include <stdint.h>
#include <cuda_runtime.h>
#include <cuda_bf16.h>
#include <cuda_fp16.h>
#include <mma.h>
#include <math.h>

using namespace nvcuda;

#define BSZ   16
#define TT    16
#define QQ    100
#define HIDD  256
#define PROJD 256
#define NI    1600    // BS*Q
#define MROWS 25600   // BS*T*Q
#define NNEG  3200
#define NJB   (NNEG / 64)      // 50 j-blocks of 64
#define MAXC  (NI / 64 + TT)   // 41 chunk slots upper bound

// -------- scratch (device globals; no allocation allowed) --------
__device__ __nv_bfloat16 g_neg_h[NNEG * TT * PROJD];
__device__ __nv_bfloat16 g_neg_l[NNEG * TT * PROJD];
__device__ float g_nsq[NNEG * TT];
__device__ __nv_bfloat16 g_a_h[NI * PROJD];
__device__ __nv_bfloat16 g_a_l[NI * PROJD];
__device__ float g_asq[NI];
__device__ float g_numer[NI];
__device__ float g_inv2s[NI];
__device__ float g_part[NI * 256];
__device__ float g_self[NI];
__device__ float g_brown[NI];
__device__ float g_ht[NI];
__device__ __half g_wt_h[PROJD * HIDD];          // W^T fp16 (single rounding)
__device__ int g_bucket_cnt[TT];
__device__ int g_bitems[TT * NI];

__device__ __forceinline__ float warp_sum(float v) {
    #pragma unroll
    for (int o = 16; o > 0; o >>= 1) v += __shfl_xor_sync(0xffffffffu, v, o);
    return v;
}

__device__ __forceinline__ uint32_t smem_u32(const void* p) {
    uint32_t a;
    asm("{ .reg .u64 t; cvta.to.shared.u64 t, %1; cvt.u32.u64 %0, t; }" : "=r"(a) : "l"(p));
    return a;
}
__device__ __forceinline__ void cp16(uint32_t dst, const void* src) {
    asm volatile("cp.async.cg.shared.global [%0], [%1], 16;" :: "r"(dst), "l"(src));
}
#define CP_COMMIT() asm volatile("cp.async.commit_group;" ::: "memory")
#define CP_WAIT0()  asm volatile("cp.async.wait_group 0;" ::: "memory")
#define CP_WAIT1()  asm volatile("cp.async.wait_group 1;" ::: "memory")

__device__ __forceinline__ void ld_rec4(const __nv_bfloat16* __restrict__ h,
                                        const __nv_bfloat16* __restrict__ l,
                                        size_t idx, float* out) {
    __nv_bfloat162 h0 = *(const __nv_bfloat162*)&h[idx];
    __nv_bfloat162 h1 = *(const __nv_bfloat162*)&h[idx + 2];
    __nv_bfloat162 l0 = *(const __nv_bfloat162*)&l[idx];
    __nv_bfloat162 l1 = *(const __nv_bfloat162*)&l[idx + 2];
    out[0] = __bfloat162float(h0.x) + __bfloat162float(l0.x);
    out[1] = __bfloat162float(h0.y) + __bfloat162float(l0.y);
    out[2] = __bfloat162float(h1.x) + __bfloat162float(l1.x);
    out[3] = __bfloat162float(h1.y) + __bfloat162float(l1.y);
}

// sorted-desc top-5 insert
__device__ __forceinline__ void ins5(float* t5, float v) {
    if (v > t5[4]) {
        if (v > t5[0])      { t5[4]=t5[3]; t5[3]=t5[2]; t5[2]=t5[1]; t5[1]=t5[0]; t5[0]=v; }
        else if (v > t5[1]) { t5[4]=t5[3]; t5[3]=t5[2]; t5[2]=t5[1]; t5[1]=v; }
        else if (v > t5[2]) { t5[4]=t5[3]; t5[3]=t5[2]; t5[2]=v; }
        else if (v > t5[3]) { t5[4]=t5[3]; t5[3]=v; }
        else                { t5[4]=v; }
    }
}

// ============ Kernel 0: W -> W^T fp16 ============
__global__ void __launch_bounds__(256) convert_w_kernel(const float* __restrict__ W)
{
    if (blockIdx.x == 0 && threadIdx.x < TT) g_bucket_cnt[threadIdx.x] = 0;
    int k = blockIdx.x;
    int n = threadIdx.x;
    g_wt_h[n * HIDD + k] = __float2half(W[k * PROJD + n]);
}

// ============ Kernel 1: fp16 2-product wmma projection (64M x 256N per CTA, 2 CTA/SM) ============
// x*W ~= Ah*Wh + Al*Wh  (A split into fp16 hi/lo; W single fp16 rounding)
#define KC   64
#define LDA  72
#define LDB  72
#define STG_LD 260

#define OFF_BIAS  0
#define OFF_U     1024
#define OFF_A_HI  (OFF_U)
#define OFF_A_LO  (OFF_A_HI + 64 * LDA * 2)
#define OFF_B_H   (OFF_A_LO + 64 * LDA * 2)
#define TILES_END (OFF_B_H + 256 * LDB * 2)      // 1024+18432+36864 = 56320
#define STG_END   (OFF_U + 64 * STG_LD * 4)      // 67584
#define PROJ_SMEM (STG_END > TILES_END ? STG_END : TILES_END)

__global__ void __launch_bounds__(256, 2) proj_mma_kernel(
    const float* __restrict__ fe, const float* __restrict__ ofe,
    const float* __restrict__ bias)
{
    extern __shared__ char smem_raw[];
    uint32_t sb = smem_u32(smem_raw);
    float* bias_s = (float*)(smem_raw + OFF_BIAS);
    __half* Ah = (__half*)(smem_raw + OFF_A_HI);
    __half* Al = (__half*)(smem_raw + OFF_A_LO);
    __half* Bh = (__half*)(smem_raw + OFF_B_H);
    float* stage = (float*)(smem_raw + OFF_U);

    int tid  = threadIdx.x;
    int wid  = tid >> 5;
    int lane = tid & 31;

    int b = blockIdx.x;
    const float* A = (b < 400) ? fe : ofe;
    int base = (b < 400) ? 0 : NI;
    int m0   = (b % 400) * 64;

    bias_s[tid] = bias[tid];

    int wm = wid >> 2;
    int wn = wid & 3;

    wmma::fragment<wmma::accumulator, 16, 16, 16, float> acc[2][4];
    #pragma unroll
    for (int mt = 0; mt < 2; mt++)
        #pragma unroll
        for (int nt = 0; nt < 4; nt++)
            wmma::fill_fragment(acc[mt][nt], 0.0f);

    for (int c = 0; c < 4; c++) {
        int k0 = c * KC;
        __syncthreads();
        // ---- issue B chunk via cp.async (overlaps A load/convert below) ----
        #pragma unroll
        for (int it = 0; it < 8; it++) {
            int flat = it * 256 + tid;       // 0..2047
            int n = flat >> 3;               // 0..255
            int u = flat & 7;                // 16B unit (8 halves)
            cp16(sb + OFF_B_H + n * (LDB * 2) + u * 16, &g_wt_h[(size_t)n * HIDD + k0 + u * 8]);
        }
        CP_COMMIT();
        // ---- load & split A chunk: 64 rows x 64 fp32 -> fp16 hi/lo ----
        #pragma unroll
        for (int it = 0; it < 4; it++) {
            int flat = it * 256 + tid;
            int row  = flat >> 4;
            int j    = flat & 15;
            float4 v = *(const float4*)&A[(size_t)(m0 + row) * HIDD + k0 + j * 4];
            __half h0 = __float2half(v.x);
            __half h1 = __float2half(v.y);
            __half h2 = __float2half(v.z);
            __half h3 = __float2half(v.w);
            __half l0 = __float2half(v.x - __half2float(h0));
            __half l1 = __float2half(v.y - __half2float(h1));
            __half l2 = __float2half(v.z - __half2float(h2));
            __half l3 = __float2half(v.w - __half2float(h3));
            int o = row * LDA + j * 4;
            *(__half2*)&Ah[o]     = __half2{h0, h1};
            *(__half2*)&Ah[o + 2] = __half2{h2, h3};
            *(__half2*)&Al[o]     = __half2{l0, l1};
            *(__half2*)&Al[o + 2] = __half2{l2, l3};
        }
        CP_WAIT0();
        __syncthreads();

        #pragma unroll
        for (int kt = 0; kt < KC / 16; kt++) {
            wmma::fragment<wmma::matrix_a, 16, 16, 16, __half, wmma::row_major> ah[2], al[2];
            #pragma unroll
            for (int mt = 0; mt < 2; mt++) {
                int row0 = wm * 32 + mt * 16;
                wmma::load_matrix_sync(ah[mt], Ah + row0 * LDA + kt * 16, LDA);
                wmma::load_matrix_sync(al[mt], Al + row0 * LDA + kt * 16, LDA);
            }
            #pragma unroll
            for (int nt = 0; nt < 4; nt++) {
                int n0 = wn * 64 + nt * 16;
                wmma::fragment<wmma::matrix_b, 16, 16, 16, __half, wmma::col_major> bh;
                wmma::load_matrix_sync(bh, Bh + n0 * LDB + kt * 16, LDB);
                #pragma unroll
                for (int mt = 0; mt < 2; mt++) {
                    wmma::mma_sync(acc[mt][nt], ah[mt], bh, acc[mt][nt]);
                    wmma::mma_sync(acc[mt][nt], al[mt], bh, acc[mt][nt]);
                }
            }
        }
    }

    __syncthreads();
    #pragma unroll
    for (int mt = 0; mt < 2; mt++) {
        int row0 = wm * 32 + mt * 16;
        #pragma unroll
        for (int nt = 0; nt < 4; nt++) {
            int n0 = wn * 64 + nt * 16;
            wmma::store_matrix_sync(stage + row0 * STG_LD + n0, acc[mt][nt],
                                    STG_LD, wmma::mem_row_major);
        }
    }
    __syncthreads();

    for (int rr = 0; rr < 8; rr++) {
        int r = wid * 8 + rr;
        float v[8];
        float ss = 0.0f;
        #pragma unroll
        for (int u = 0; u < 8; u++) {
            int cidx = lane + 32 * u;
            float x = stage[r * STG_LD + cidx] + bias_s[cidx];
            v[u] = x;
            ss += x * x;
        }
        ss = warp_sum(ss);
        float inv = rsqrtf(ss);
        int m = m0 + r;
        int q = m % QQ;
        int t = (m / QQ) % TT;
        int bs = m / (QQ * TT);
        int orow = (base + bs * QQ + q) * TT + t;
        #pragma unroll
        for (int u = 0; u < 8; u++) {
            float x = v[u] * inv;
            __nv_bfloat16 h = __float2bfloat16(x);
            size_t o = (size_t)orow * PROJD + lane + 32 * u;
            g_neg_h[o] = h;
            g_neg_l[o] = __float2bfloat16(x - __bfloat162float(h));
        }
        if (lane == 0) g_nsq[orow] = ss * inv * inv;
    }
}

// ============ Kernel 2: bridge prep + fused head-tail + bucket push ============
__global__ void __launch_bounds__(256) bridge_prep_kernel(const int* __restrict__ bridge)
{
    int warp = threadIdx.x >> 5;
    int lane = threadIdx.x & 31;
    int i = blockIdx.x * 8 + warp;
    int bh = bridge[i * 3 + 0];
    int bp = bridge[i * 3 + 1];
    int bt = bridge[i * 3 + 2];
    float bhf = (float)bh, bpf = (float)bp, btf = (float)bt;
    float alpha = (bpf - bhf) / (btf - bhf);
    float sigma = alpha * (btf - bpf);
    float inv2s = 1.0f / (2.0f * sigma * sigma);

    size_t r0 = (size_t)(i * TT + bh) * PROJD;
    size_t r1 = (size_t)(i * TT + bp) * PROJD;
    size_t r2 = (size_t)(i * TT + bt) * PROJD;
    size_t rh = (size_t)(i * TT + 0) * PROJD;
    size_t rt = (size_t)(i * TT + (TT - 1)) * PROJD;
    float oma = 1.0f - alpha;
    float xs = 0.0f, as = 0.0f, ht = 0.0f;
    #pragma unroll
    for (int h = 0; h < 2; h++) {
        int c = h * 128 + lane * 4;
        float g0[4], g1[4], g2[4], gh[4], gt[4];
        ld_rec4(g_neg_h, g_neg_l, r0 + c, g0);
        ld_rec4(g_neg_h, g_neg_l, r1 + c, g1);
        ld_rec4(g_neg_h, g_neg_l, r2 + c, g2);
        ld_rec4(g_neg_h, g_neg_l, rh + c, gh);
        ld_rec4(g_neg_h, g_neg_l, rt + c, gt);
        #pragma unroll
        for (int e = 0; e < 4; e++) {
            float aa = oma * g0[e] + alpha * g2[e];
            float x  = g1[e] - oma * g0[e] - alpha * g2[e];
            xs += x * x;
            as += aa * aa;
            ht += gh[e] * gt[e];
            __nv_bfloat16 ahv = __float2bfloat16(aa);
            size_t o = (size_t)i * PROJD + c + e;
            g_a_h[o] = ahv;
            g_a_l[o] = __float2bfloat16(aa - __bfloat162float(ahv));
        }
    }
    xs = warp_sum(xs);
    as = warp_sum(as);
    ht = warp_sum(ht);
    if (lane == 0) {
        g_inv2s[i] = inv2s;
        g_asq[i]   = as;
        g_numer[i] = expf(-xs * inv2s);
        float z = 0.3f - ht;
        g_ht[i] = log1pf(expf(z));
        int pos = atomicAdd(&g_bucket_cnt[bp], 1);
        g_bitems[bp * NI + pos] = i;
    }
}

// ============ Kernel 3: dist GEMM — 64i x 64j per CTA, 3 CTAs/SM, cp.async pipeline ============
#define DKC   64
#define DLD3  72
#define DSTG3 72
#define DS_AH   0
#define DS_AL   9216
#define DS_BH   18432
#define DS_BL   27648
#define DS_SZ   36864
#define D3_IDX  (2 * DS_SZ)
#define D3_NSQ  (D3_IDX + 64 * 4)
#define DIST_SMEM (D3_NSQ + 64 * 4 + 16)

__global__ void __launch_bounds__(256, 3) dist_mma_kernel()
{
    extern __shared__ char smem_raw[];
    uint32_t sbase = smem_u32(smem_raw);
    float* stage = (float*)(smem_raw);
    int* sitems = (int*)(smem_raw + D3_IDX);
    float* snsq = (float*)(smem_raw + D3_NSQ);

    int cidx = blockIdx.y;
    int t = -1, off = 0;
    {
        int acc_c = 0;
        #pragma unroll
        for (int tt2 = 0; tt2 < TT; tt2++) {
            int nch = (g_bucket_cnt[tt2] + 63) >> 6;
            if (t < 0 && cidx < acc_c + nch) { t = tt2; off = (cidx - acc_c) * 64; }
            acc_c += nch;
        }
    }
    if (t < 0) return;
    int cc = min(64, g_bucket_cnt[t] - off);
    int jblock = blockIdx.x;
    int j0 = jblock * 64;

    int tid = threadIdx.x;
    int wid = tid >> 5;
    int wm = wid >> 2;
    int wn = wid & 3;

    if (tid < 64) {
        sitems[tid] = g_bitems[t * NI + off + ((tid < cc) ? tid : 0)];
        snsq[tid]   = g_nsq[(j0 + tid) * TT + t];
    }
    __syncthreads();

    int l_r0 = tid >> 3;
    int l_k  = tid & 7;
    int ai0 = sitems[l_r0];
    int ai1 = sitems[32 + l_r0];

    wmma::fragment<wmma::accumulator, 16, 16, 16, float> acc[2];
    wmma::fill_fragment(acc[0], 0.0f);
    wmma::fill_fragment(acc[1], 0.0f);

    auto prefetch = [&](int c, int buf) {
        int kbase = c * DKC;
        uint32_t st = sbase + buf * DS_SZ;
        uint32_t d0 = st + l_r0 * 144 + l_k * 16;
        uint32_t d1 = st + (32 + l_r0) * 144 + l_k * 16;
        size_t sa0 = (size_t)ai0 * PROJD + kbase + l_k * 8;
        size_t sa1 = (size_t)ai1 * PROJD + kbase + l_k * 8;
        cp16(d0 + DS_AH, &g_a_h[sa0]);
        cp16(d1 + DS_AH, &g_a_h[sa1]);
        cp16(d0 + DS_AL, &g_a_l[sa0]);
        cp16(d1 + DS_AL, &g_a_l[sa1]);
        size_t sb0 = (size_t)((j0 + l_r0) * TT + t) * PROJD + kbase + l_k * 8;
        size_t sb1 = (size_t)((j0 + 32 + l_r0) * TT + t) * PROJD + kbase + l_k * 8;
        cp16(d0 + DS_BH, &g_neg_h[sb0]);
        cp16(d1 + DS_BH, &g_neg_h[sb1]);
        cp16(d0 + DS_BL, &g_neg_l[sb0]);
        cp16(d1 + DS_BL, &g_neg_l[sb1]);
    };

    prefetch(0, 0);
    CP_COMMIT();

    #pragma unroll
    for (int c = 0; c < 4; c++) {
        int buf = c & 1;
        if (c < 3) { prefetch(c + 1, (c + 1) & 1); CP_COMMIT(); CP_WAIT1(); }
        else       { CP_WAIT0(); }
        __syncthreads();

        const __nv_bfloat16* Ah = (const __nv_bfloat16*)(smem_raw + buf * DS_SZ + DS_AH);
        const __nv_bfloat16* Al = (const __nv_bfloat16*)(smem_raw + buf * DS_SZ + DS_AL);
        const __nv_bfloat16* Bh = (const __nv_bfloat16*)(smem_raw + buf * DS_SZ + DS_BH);
        const __nv_bfloat16* Bl = (const __nv_bfloat16*)(smem_raw + buf * DS_SZ + DS_BL);

        #pragma unroll
        for (int kt = 0; kt < DKC / 16; kt++) {
            wmma::fragment<wmma::matrix_a, 16, 16, 16, __nv_bfloat16, wmma::row_major> ah[2], al[2];
            #pragma unroll
            for (int mt = 0; mt < 2; mt++) {
                int row0 = wm * 32 + mt * 16;
                wmma::load_matrix_sync(ah[mt], Ah + row0 * DLD3 + kt * 16, DLD3);
                wmma::load_matrix_sync(al[mt], Al + row0 * DLD3 + kt * 16, DLD3);
            }
            wmma::fragment<wmma::matrix_b, 16, 16, 16, __nv_bfloat16, wmma::col_major> bh, bl;
            wmma::load_matrix_sync(bh, Bh + (wn * 16) * DLD3 + kt * 16, DLD3);
            wmma::load_matrix_sync(bl, Bl + (wn * 16) * DLD3 + kt * 16, DLD3);
            #pragma unroll
            for (int mt = 0; mt < 2; mt++) {
                wmma::mma_sync(acc[mt], ah[mt], bh, acc[mt]);
                wmma::mma_sync(acc[mt], al[mt], bh, acc[mt]);
                wmma::mma_sync(acc[mt], ah[mt], bl, acc[mt]);
            }
        }
        __syncthreads();
    }

    #pragma unroll
    for (int mt = 0; mt < 2; mt++)
        wmma::store_matrix_sync(stage + (wm * 32 + mt * 16) * DSTG3 + wn * 16,
                                acc[mt], DSTG3, wmma::mem_row_major);
    __syncthreads();

    int r  = tid >> 2;
    int c0 = (tid & 3) * 16;
    int i = sitems[r];
    bool valid = (r < cc);
    float asqi = g_asq[i];
    float is2  = g_inv2s[i];
    float t5[5] = {-1e30f, -1e30f, -1e30f, -1e30f, -1e30f};
    #pragma unroll
    for (int u = 0; u < 16; u++) {
        int j = j0 + c0 + u;
        float cross = stage[r * DSTG3 + c0 + u];
        float d = -(snsq[c0 + u] - 2.0f * cross + asqi) * is2;
        if (j == i) { if (valid) g_self[i] = d; d = -10000.0f; }
        ins5(t5, d);
    }
    #pragma unroll
    for (int o2 = 1; o2 <= 2; o2 <<= 1) {
        float b0 = __shfl_xor_sync(0xffffffffu, t5[0], o2);
        float b1 = __shfl_xor_sync(0xffffffffu, t5[1], o2);
        float b2 = __shfl_xor_sync(0xffffffffu, t5[2], o2);
        float b3 = __shfl_xor_sync(0xffffffffu, t5[3], o2);
        float b4 = __shfl_xor_sync(0xffffffffu, t5[4], o2);
        ins5(t5, b0); ins5(t5, b1); ins5(t5, b2); ins5(t5, b3); ins5(t5, b4);
    }
    if (valid && (tid & 3) == 0) {
        float* dst = &g_part[(size_t)i * 256 + jblock * 5];
        dst[0] = t5[0]; dst[1] = t5[1]; dst[2] = t5[2]; dst[3] = t5[3]; dst[4] = t5[4];
    }
}

// ============ Kernel 4: warp-per-row merge of partial top-5s ============
__global__ void __launch_bounds__(256) topk_kernel()
{
    int wid  = threadIdx.x >> 5;
    int lane = threadIdx.x & 31;
    int i = blockIdx.x * 8 + wid;
    const float* part = &g_part[(size_t)i * 256];

    float t5[5] = {-1e30f, -1e30f, -1e30f, -1e30f, -1e30f};
    for (int k = lane; k < NJB * 5; k += 32) ins5(t5, part[k]);
    #pragma unroll
    for (int off = 16; off > 0; off >>= 1) {
        float b0 = __shfl_xor_sync(0xffffffffu, t5[0], off);
        float b1 = __shfl_xor_sync(0xffffffffu, t5[1], off);
        float b2 = __shfl_xor_sync(0xffffffffu, t5[2], off);
        float b3 = __shfl_xor_sync(0xffffffffu, t5[3], off);
        float b4 = __shfl_xor_sync(0xffffffffu, t5[4], off);
        ins5(t5, b0); ins5(t5, b1); ins5(t5, b2); ins5(t5, b3); ins5(t5, b4);
    }
    if (lane == 0) {
        float deno = expf(g_self[i]);
        #pragma unroll
        for (int k = 0; k < 5; k++) deno += expf(t5[k]);
        g_brown[i] = g_numer[i] / deno;
    }
}

// ============ Kernel 5: deterministic final reduction ============
__global__ void __launch_bounds__(256) final_kernel(float* __restrict__ out)
{
    __shared__ float sb[256], sh[256];
    int tid = threadIdx.x;
    float b = 0.0f, h = 0.0f;
    for (int i = tid; i < NI; i += 256) { b += g_brown[i]; h += g_ht[i]; }
    sb[tid] = b; sh[tid] = h;
    __syncthreads();
    for (int s = 128; s > 0; s >>= 1) {
        if (tid < s) { sb[tid] += sb[tid + s]; sh[tid] += sh[tid + s]; }
        __syncthreads();
    }
    if (tid == 0) {
        out[0] = sb[0] / (float)NI;
        out[1] = sh[0] / (float)NI;
    }
}

// ==================== launch ====================
extern "C" void kernel_launch(void* const* d_in, const int* in_sizes, int n_in,
                              void* d_out, int out_size)
{
    const float* fe     = (const float*)d_in[0];
    const float* ofe    = (const float*)d_in[1];
    const float* W      = (const float*)d_in[2];
    const float* bias   = (const float*)d_in[3];
    const int*   bridge = (const int*)d_in[4];
    float* out = (float*)d_out;

    cudaFuncSetAttribute(proj_mma_kernel, cudaFuncAttributeMaxDynamicSharedMemorySize, PROJ_SMEM);
    cudaFuncSetAttribute(dist_mma_kernel, cudaFuncAttributeMaxDynamicSharedMemorySize, DIST_SMEM);

    convert_w_kernel<<<HIDD, PROJD>>>(W);
    proj_mma_kernel<<<800, 256, PROJ_SMEM>>>(fe, ofe, bias);

    bridge_prep_kernel<<<NI / 8, 256>>>(bridge);
    dist_mma_kernel<<<dim3(NJB, MAXC), 256, DIST_SMEM>>>();
    topk_kernel<<<NI / 8, 256>>>();
    final_kernel<<<1, 256>>>(out);
}

// round 15
// speedup vs baseline: 1.4883x; 1.0621x over previous
#include <cstdint>
#include <stdint.h>
#include <cuda_runtime.h>
#include <cuda_bf16.h>
#include <cuda_fp16.h>
#include <mma.h>
#include <math.h>

using namespace nvcuda;

#define BSZ   16
#define TT    16
#define QQ    100
#define HIDD  256
#define PROJD 256
#define NI    1600    // BS*Q
#define MROWS 25600   // BS*T*Q
#define NNEG  3200
#define NJB   (NNEG / 64)      // 50 j-blocks of 64
#define MAXC  (NI / 64 + TT)   // 41 chunk slots upper bound

// -------- scratch (device globals; no allocation allowed) --------
__device__ __half g_neg_h[NNEG * TT * PROJD];
__device__ __half g_neg_l[NNEG * TT * PROJD];
__device__ float g_nsq[NNEG * TT];
__device__ __half g_a_h[NI * PROJD];
__device__ __half g_a_l[NI * PROJD];
__device__ float g_asq[NI];
__device__ float g_numer[NI];
__device__ float g_inv2s[NI];
__device__ float g_part[NI * 256];
__device__ float g_self[NI];
__device__ float g_brown[NI];
__device__ float g_ht[NI];
__device__ __half g_wt_h[PROJD * HIDD];          // W^T fp16 (single rounding)
__device__ int g_bucket_cnt[TT];
__device__ int g_bitems[TT * NI];

__device__ __forceinline__ float warp_sum(float v) {
    #pragma unroll
    for (int o = 16; o > 0; o >>= 1) v += __shfl_xor_sync(0xffffffffu, v, o);
    return v;
}

__device__ __forceinline__ uint32_t smem_u32(const void* p) {
    uint32_t a;
    asm("{ .reg .u64 t; cvta.to.shared.u64 t, %1; cvt.u32.u64 %0, t; }" : "=r"(a) : "l"(p));
    return a;
}
__device__ __forceinline__ void cp16(uint32_t dst, const void* src) {
    asm volatile("cp.async.cg.shared.global [%0], [%1], 16;" :: "r"(dst), "l"(src));
}
#define CP_COMMIT() asm volatile("cp.async.commit_group;" ::: "memory")
#define CP_WAIT0()  asm volatile("cp.async.wait_group 0;" ::: "memory")
#define CP_WAIT1()  asm volatile("cp.async.wait_group 1;" ::: "memory")

// reconstruct 4 floats from fp16 hi/lo arrays at index idx (8B aligned)
__device__ __forceinline__ void ld_rec4(const __half* __restrict__ h,
                                        const __half* __restrict__ l,
                                        size_t idx, float* out) {
    __half2 h0 = *(const __half2*)&h[idx];
    __half2 h1 = *(const __half2*)&h[idx + 2];
    __half2 l0 = *(const __half2*)&l[idx];
    __half2 l1 = *(const __half2*)&l[idx + 2];
    out[0] = __half2float(h0.x) + __half2float(l0.x);
    out[1] = __half2float(h0.y) + __half2float(l0.y);
    out[2] = __half2float(h1.x) + __half2float(l1.x);
    out[3] = __half2float(h1.y) + __half2float(l1.y);
}

// sorted-desc top-5 insert
__device__ __forceinline__ void ins5(float* t5, float v) {
    if (v > t5[4]) {
        if (v > t5[0])      { t5[4]=t5[3]; t5[3]=t5[2]; t5[2]=t5[1]; t5[1]=t5[0]; t5[0]=v; }
        else if (v > t5[1]) { t5[4]=t5[3]; t5[3]=t5[2]; t5[2]=t5[1]; t5[1]=v; }
        else if (v > t5[2]) { t5[4]=t5[3]; t5[3]=t5[2]; t5[2]=v; }
        else if (v > t5[3]) { t5[4]=t5[3]; t5[3]=v; }
        else                { t5[4]=v; }
    }
}

// ============ Kernel 0: W -> W^T fp16 ============
__global__ void __launch_bounds__(256) convert_w_kernel(const float* __restrict__ W)
{
    if (blockIdx.x == 0 && threadIdx.x < TT) g_bucket_cnt[threadIdx.x] = 0;
    int k = blockIdx.x;
    int n = threadIdx.x;
    g_wt_h[n * HIDD + k] = __float2half(W[k * PROJD + n]);
}

// ============ Kernel 1: fp16 2-product wmma projection (64M x 256N per CTA, 2 CTA/SM) ============
#define KC   64
#define LDA  72
#define LDB  72
#define STG_LD 260

#define OFF_BIAS  0
#define OFF_U     1024
#define OFF_A_HI  (OFF_U)
#define OFF_A_LO  (OFF_A_HI + 64 * LDA * 2)
#define OFF_B_H   (OFF_A_LO + 64 * LDA * 2)
#define TILES_END (OFF_B_H + 256 * LDB * 2)
#define STG_END   (OFF_U + 64 * STG_LD * 4)
#define PROJ_SMEM (STG_END > TILES_END ? STG_END : TILES_END)

__global__ void __launch_bounds__(256, 2) proj_mma_kernel(
    const float* __restrict__ fe, const float* __restrict__ ofe,
    const float* __restrict__ bias)
{
    extern __shared__ char smem_raw[];
    uint32_t sb = smem_u32(smem_raw);
    float* bias_s = (float*)(smem_raw + OFF_BIAS);
    __half* Ah = (__half*)(smem_raw + OFF_A_HI);
    __half* Al = (__half*)(smem_raw + OFF_A_LO);
    __half* Bh = (__half*)(smem_raw + OFF_B_H);
    float* stage = (float*)(smem_raw + OFF_U);

    int tid  = threadIdx.x;
    int wid  = tid >> 5;
    int lane = tid & 31;

    int b = blockIdx.x;
    const float* A = (b < 400) ? fe : ofe;
    int base = (b < 400) ? 0 : NI;
    int m0   = (b % 400) * 64;

    bias_s[tid] = bias[tid];

    int wm = wid >> 2;
    int wn = wid & 3;

    wmma::fragment<wmma::accumulator, 16, 16, 16, float> acc[2][4];
    #pragma unroll
    for (int mt = 0; mt < 2; mt++)
        #pragma unroll
        for (int nt = 0; nt < 4; nt++)
            wmma::fill_fragment(acc[mt][nt], 0.0f);

    for (int c = 0; c < 4; c++) {
        int k0 = c * KC;
        __syncthreads();
        #pragma unroll
        for (int it = 0; it < 8; it++) {
            int flat = it * 256 + tid;
            int n = flat >> 3;
            int u = flat & 7;
            cp16(sb + OFF_B_H + n * (LDB * 2) + u * 16, &g_wt_h[(size_t)n * HIDD + k0 + u * 8]);
        }
        CP_COMMIT();
        #pragma unroll
        for (int it = 0; it < 4; it++) {
            int flat = it * 256 + tid;
            int row  = flat >> 4;
            int j    = flat & 15;
            float4 v = *(const float4*)&A[(size_t)(m0 + row) * HIDD + k0 + j * 4];
            __half h0 = __float2half(v.x);
            __half h1 = __float2half(v.y);
            __half h2 = __float2half(v.z);
            __half h3 = __float2half(v.w);
            __half l0 = __float2half(v.x - __half2float(h0));
            __half l1 = __float2half(v.y - __half2float(h1));
            __half l2 = __float2half(v.z - __half2float(h2));
            __half l3 = __float2half(v.w - __half2float(h3));
            int o = row * LDA + j * 4;
            *(__half2*)&Ah[o]     = __half2{h0, h1};
            *(__half2*)&Ah[o + 2] = __half2{h2, h3};
            *(__half2*)&Al[o]     = __half2{l0, l1};
            *(__half2*)&Al[o + 2] = __half2{l2, l3};
        }
        CP_WAIT0();
        __syncthreads();

        #pragma unroll
        for (int kt = 0; kt < KC / 16; kt++) {
            wmma::fragment<wmma::matrix_a, 16, 16, 16, __half, wmma::row_major> ah[2], al[2];
            #pragma unroll
            for (int mt = 0; mt < 2; mt++) {
                int row0 = wm * 32 + mt * 16;
                wmma::load_matrix_sync(ah[mt], Ah + row0 * LDA + kt * 16, LDA);
                wmma::load_matrix_sync(al[mt], Al + row0 * LDA + kt * 16, LDA);
            }
            #pragma unroll
            for (int nt = 0; nt < 4; nt++) {
                int n0 = wn * 64 + nt * 16;
                wmma::fragment<wmma::matrix_b, 16, 16, 16, __half, wmma::col_major> bh;
                wmma::load_matrix_sync(bh, Bh + n0 * LDB + kt * 16, LDB);
                #pragma unroll
                for (int mt = 0; mt < 2; mt++) {
                    wmma::mma_sync(acc[mt][nt], ah[mt], bh, acc[mt][nt]);
                    wmma::mma_sync(acc[mt][nt], al[mt], bh, acc[mt][nt]);
                }
            }
        }
    }

    __syncthreads();
    #pragma unroll
    for (int mt = 0; mt < 2; mt++) {
        int row0 = wm * 32 + mt * 16;
        #pragma unroll
        for (int nt = 0; nt < 4; nt++) {
            int n0 = wn * 64 + nt * 16;
            wmma::store_matrix_sync(stage + row0 * STG_LD + n0, acc[mt][nt],
                                    STG_LD, wmma::mem_row_major);
        }
    }
    __syncthreads();

    for (int rr = 0; rr < 8; rr++) {
        int r = wid * 8 + rr;
        float v[8];
        float ss = 0.0f;
        #pragma unroll
        for (int u = 0; u < 8; u++) {
            int cidx = lane + 32 * u;
            float x = stage[r * STG_LD + cidx] + bias_s[cidx];
            v[u] = x;
            ss += x * x;
        }
        ss = warp_sum(ss);
        float inv = rsqrtf(ss);
        int m = m0 + r;
        int q = m % QQ;
        int t = (m / QQ) % TT;
        int bs = m / (QQ * TT);
        int orow = (base + bs * QQ + q) * TT + t;
        #pragma unroll
        for (int u = 0; u < 8; u++) {
            float x = v[u] * inv;
            __half h = __float2half(x);
            size_t o = (size_t)orow * PROJD + lane + 32 * u;
            g_neg_h[o] = h;
            g_neg_l[o] = __float2half(x - __half2float(h));
        }
        if (lane == 0) g_nsq[orow] = ss * inv * inv;
    }
}

// ============ Kernel 2: bridge prep + fused head-tail + bucket push ============
__global__ void __launch_bounds__(256) bridge_prep_kernel(const int* __restrict__ bridge)
{
    int warp = threadIdx.x >> 5;
    int lane = threadIdx.x & 31;
    int i = blockIdx.x * 8 + warp;
    int bh = bridge[i * 3 + 0];
    int bp = bridge[i * 3 + 1];
    int bt = bridge[i * 3 + 2];
    float bhf = (float)bh, bpf = (float)bp, btf = (float)bt;
    float alpha = (bpf - bhf) / (btf - bhf);
    float sigma = alpha * (btf - bpf);
    float inv2s = 1.0f / (2.0f * sigma * sigma);

    size_t r0 = (size_t)(i * TT + bh) * PROJD;
    size_t r1 = (size_t)(i * TT + bp) * PROJD;
    size_t r2 = (size_t)(i * TT + bt) * PROJD;
    size_t rh = (size_t)(i * TT + 0) * PROJD;
    size_t rt = (size_t)(i * TT + (TT - 1)) * PROJD;
    float oma = 1.0f - alpha;
    float xs = 0.0f, as = 0.0f, ht = 0.0f;
    #pragma unroll
    for (int h = 0; h < 2; h++) {
        int c = h * 128 + lane * 4;
        float g0[4], g1[4], g2[4], gh[4], gt[4];
        ld_rec4(g_neg_h, g_neg_l, r0 + c, g0);
        ld_rec4(g_neg_h, g_neg_l, r1 + c, g1);
        ld_rec4(g_neg_h, g_neg_l, r2 + c, g2);
        ld_rec4(g_neg_h, g_neg_l, rh + c, gh);
        ld_rec4(g_neg_h, g_neg_l, rt + c, gt);
        #pragma unroll
        for (int e = 0; e < 4; e++) {
            float aa = oma * g0[e] + alpha * g2[e];
            float x  = g1[e] - oma * g0[e] - alpha * g2[e];
            xs += x * x;
            as += aa * aa;
            ht += gh[e] * gt[e];
            __half ahv = __float2half(aa);
            size_t o = (size_t)i * PROJD + c + e;
            g_a_h[o] = ahv;
            g_a_l[o] = __float2half(aa - __half2float(ahv));
        }
    }
    xs = warp_sum(xs);
    as = warp_sum(as);
    ht = warp_sum(ht);
    if (lane == 0) {
        g_inv2s[i] = inv2s;
        g_asq[i]   = as;
        g_numer[i] = expf(-xs * inv2s);
        float z = 0.3f - ht;
        g_ht[i] = log1pf(expf(z));
        int pos = atomicAdd(&g_bucket_cnt[bp], 1);
        g_bitems[bp * NI + pos] = i;
    }
}

// ============ Kernel 3: dist GEMM — fp16 2-product, 64i x 64j, 3 CTAs/SM ============
// cross ~= Ah*Bh + Al*Bh  (B lo dropped)
#define DKC   64
#define DLD3  72
#define DSTG3 72
#define DS_AH   0
#define DS_AL   9216
#define DS_BH   18432
#define DS_SZ   27648
#define D3_IDX  (2 * DS_SZ)                 // 55296
#define D3_NSQ  (D3_IDX + 64 * 4)
#define DIST_SMEM (D3_NSQ + 64 * 4 + 16)    // ~55.9 KB

__global__ void __launch_bounds__(256, 3) dist_mma_kernel()
{
    extern __shared__ char smem_raw[];
    uint32_t sbase = smem_u32(smem_raw);
    float* stage = (float*)(smem_raw);
    int* sitems = (int*)(smem_raw + D3_IDX);
    float* snsq = (float*)(smem_raw + D3_NSQ);

    int cidx = blockIdx.y;
    int t = -1, off = 0;
    {
        int acc_c = 0;
        #pragma unroll
        for (int tt2 = 0; tt2 < TT; tt2++) {
            int nch = (g_bucket_cnt[tt2] + 63) >> 6;
            if (t < 0 && cidx < acc_c + nch) { t = tt2; off = (cidx - acc_c) * 64; }
            acc_c += nch;
        }
    }
    if (t < 0) return;
    int cc = min(64, g_bucket_cnt[t] - off);
    int jblock = blockIdx.x;
    int j0 = jblock * 64;

    int tid = threadIdx.x;
    int wid = tid >> 5;
    int wm = wid >> 2;
    int wn = wid & 3;

    if (tid < 64) {
        sitems[tid] = g_bitems[t * NI + off + ((tid < cc) ? tid : 0)];
        snsq[tid]   = g_nsq[(j0 + tid) * TT + t];
    }
    __syncthreads();

    int l_r0 = tid >> 3;
    int l_k  = tid & 7;
    int ai0 = sitems[l_r0];
    int ai1 = sitems[32 + l_r0];

    wmma::fragment<wmma::accumulator, 16, 16, 16, float> acc[2];
    wmma::fill_fragment(acc[0], 0.0f);
    wmma::fill_fragment(acc[1], 0.0f);

    auto prefetch = [&](int c, int buf) {
        int kbase = c * DKC;
        uint32_t st = sbase + buf * DS_SZ;
        uint32_t d0 = st + l_r0 * 144 + l_k * 16;
        uint32_t d1 = st + (32 + l_r0) * 144 + l_k * 16;
        size_t sa0 = (size_t)ai0 * PROJD + kbase + l_k * 8;
        size_t sa1 = (size_t)ai1 * PROJD + kbase + l_k * 8;
        cp16(d0 + DS_AH, &g_a_h[sa0]);
        cp16(d1 + DS_AH, &g_a_h[sa1]);
        cp16(d0 + DS_AL, &g_a_l[sa0]);
        cp16(d1 + DS_AL, &g_a_l[sa1]);
        size_t sb0 = (size_t)((j0 + l_r0) * TT + t) * PROJD + kbase + l_k * 8;
        size_t sb1 = (size_t)((j0 + 32 + l_r0) * TT + t) * PROJD + kbase + l_k * 8;
        cp16(d0 + DS_BH, &g_neg_h[sb0]);
        cp16(d1 + DS_BH, &g_neg_h[sb1]);
    };

    prefetch(0, 0);
    CP_COMMIT();

    #pragma unroll
    for (int c = 0; c < 4; c++) {
        int buf = c & 1;
        if (c < 3) { prefetch(c + 1, (c + 1) & 1); CP_COMMIT(); CP_WAIT1(); }
        else       { CP_WAIT0(); }
        __syncthreads();

        const __half* Ah = (const __half*)(smem_raw + buf * DS_SZ + DS_AH);
        const __half* Al = (const __half*)(smem_raw + buf * DS_SZ + DS_AL);
        const __half* Bh = (const __half*)(smem_raw + buf * DS_SZ + DS_BH);

        #pragma unroll
        for (int kt = 0; kt < DKC / 16; kt++) {
            wmma::fragment<wmma::matrix_a, 16, 16, 16, __half, wmma::row_major> ah[2], al[2];
            #pragma unroll
            for (int mt = 0; mt < 2; mt++) {
                int row0 = wm * 32 + mt * 16;
                wmma::load_matrix_sync(ah[mt], Ah + row0 * DLD3 + kt * 16, DLD3);
                wmma::load_matrix_sync(al[mt], Al + row0 * DLD3 + kt * 16, DLD3);
            }
            wmma::fragment<wmma::matrix_b, 16, 16, 16, __half, wmma::col_major> bh;
            wmma::load_matrix_sync(bh, Bh + (wn * 16) * DLD3 + kt * 16, DLD3);
            #pragma unroll
            for (int mt = 0; mt < 2; mt++) {
                wmma::mma_sync(acc[mt], ah[mt], bh, acc[mt]);
                wmma::mma_sync(acc[mt], al[mt], bh, acc[mt]);
            }
        }
        __syncthreads();
    }

    #pragma unroll
    for (int mt = 0; mt < 2; mt++)
        wmma::store_matrix_sync(stage + (wm * 32 + mt * 16) * DSTG3 + wn * 16,
                                acc[mt], DSTG3, wmma::mem_row_major);
    __syncthreads();

    int r  = tid >> 2;
    int c0 = (tid & 3) * 16;
    int i = sitems[r];
    bool valid = (r < cc);
    float asqi = g_asq[i];
    float is2  = g_inv2s[i];
    float t5[5] = {-1e30f, -1e30f, -1e30f, -1e30f, -1e30f};
    #pragma unroll
    for (int u = 0; u < 16; u++) {
        int j = j0 + c0 + u;
        float cross = stage[r * DSTG3 + c0 + u];
        float d = -(snsq[c0 + u] - 2.0f * cross + asqi) * is2;
        if (j == i) { if (valid) g_self[i] = d; d = -10000.0f; }
        ins5(t5, d);
    }
    #pragma unroll
    for (int o2 = 1; o2 <= 2; o2 <<= 1) {
        float b0 = __shfl_xor_sync(0xffffffffu, t5[0], o2);
        float b1 = __shfl_xor_sync(0xffffffffu, t5[1], o2);
        float b2 = __shfl_xor_sync(0xffffffffu, t5[2], o2);
        float b3 = __shfl_xor_sync(0xffffffffu, t5[3], o2);
        float b4 = __shfl_xor_sync(0xffffffffu, t5[4], o2);
        ins5(t5, b0); ins5(t5, b1); ins5(t5, b2); ins5(t5, b3); ins5(t5, b4);
    }
    if (valid && (tid & 3) == 0) {
        float* dst = &g_part[(size_t)i * 256 + jblock * 5];
        dst[0] = t5[0]; dst[1] = t5[1]; dst[2] = t5[2]; dst[3] = t5[3]; dst[4] = t5[4];
    }
}

// ============ Kernel 4: warp-per-row merge of partial top-5s ============
__global__ void __launch_bounds__(256) topk_kernel()
{
    int wid  = threadIdx.x >> 5;
    int lane = threadIdx.x & 31;
    int i = blockIdx.x * 8 + wid;
    const float* part = &g_part[(size_t)i * 256];

    float t5[5] = {-1e30f, -1e30f, -1e30f, -1e30f, -1e30f};
    for (int k = lane; k < NJB * 5; k += 32) ins5(t5, part[k]);
    #pragma unroll
    for (int off = 16; off > 0; off >>= 1) {
        float b0 = __shfl_xor_sync(0xffffffffu, t5[0], off);
        float b1 = __shfl_xor_sync(0xffffffffu, t5[1], off);
        float b2 = __shfl_xor_sync(0xffffffffu, t5[2], off);
        float b3 = __shfl_xor_sync(0xffffffffu, t5[3], off);
        float b4 = __shfl_xor_sync(0xffffffffu, t5[4], off);
        ins5(t5, b0); ins5(t5, b1); ins5(t5, b2); ins5(t5, b3); ins5(t5, b4);
    }
    if (lane == 0) {
        float deno = expf(g_self[i]);
        #pragma unroll
        for (int k = 0; k < 5; k++) deno += expf(t5[k]);
        g_brown[i] = g_numer[i] / deno;
    }
}

// ============ Kernel 5: deterministic final reduction ============
__global__ void __launch_bounds__(256) final_kernel(float* __restrict__ out)
{
    __shared__ float sb[256], sh[256];
    int tid = threadIdx.x;
    float b = 0.0f, h = 0.0f;
    for (int i = tid; i < NI; i += 256) { b += g_brown[i]; h += g_ht[i]; }
    sb[tid] = b; sh[tid] = h;
    __syncthreads();
    for (int s = 128; s > 0; s >>= 1) {
        if (tid < s) { sb[tid] += sb[tid + s]; sh[tid] += sh[tid + s]; }
        __syncthreads();
    }
    if (tid == 0) {
        out[0] = sb[0] / (float)NI;
        out[1] = sh[0] / (float)NI;
    }
}

// ==================== launch ====================
extern "C" void kernel_launch(void* const* d_in, const int* in_sizes, int n_in,
                              void* d_out, int out_size)
{
    const float* fe     = (const float*)d_in[0];
    const float* ofe    = (const float*)d_in[1];
    const float* W      = (const float*)d_in[2];
    const float* bias   = (const float*)d_in[3];
    const int*   bridge = (const int*)d_in[4];
    float* out = (float*)d_out;

    cudaFuncSetAttribute(proj_mma_kernel, cudaFuncAttributeMaxDynamicSharedMemorySize, PROJ_SMEM);
    cudaFuncSetAttribute(dist_mma_kernel, cudaFuncAttributeMaxDynamicSharedMemorySize, DIST_SMEM);

    convert_w_kernel<<<HIDD, PROJD>>>(W);
    proj_mma_kernel<<<800, 256, PROJ_SMEM>>>(fe, ofe, bias);

    bridge_prep_kernel<<<NI / 8, 256>>>(bridge);
    dist_mma_kernel<<<dim3(NJB, MAXC), 256, DIST_SMEM>>>();
    topk_kernel<<<NI / 8, 256>>>();
    final_kernel<<<1, 256>>>(out);
}

// round 16
// speedup vs baseline: 1.6053x; 1.0786x over previous
#include <cstdint>
#include <stdint.h>
#include <cuda_runtime.h>
#include <cuda_bf16.h>
#include <cuda_fp16.h>
#include <mma.h>
#include <math.h>

using namespace nvcuda;

#define BSZ   16
#define TT    16
#define QQ    100
#define HIDD  256
#define PROJD 256
#define NI    1600    // BS*Q
#define MROWS 25600   // BS*T*Q
#define NNEG  3200
#define NJB   (NNEG / 64)      // 50 j-blocks of 64
#define MAXC  (NI / 64 + TT)   // 41 chunk slots upper bound

// -------- scratch (device globals; no allocation allowed) --------
__device__ __half g_neg_h[NNEG * TT * PROJD];
__device__ __half g_neg_l[NNEG * TT * PROJD];
__device__ float g_nsq[NNEG * TT];
__device__ __half g_a_h[NI * PROJD];
__device__ float g_asq[NI];
__device__ float g_numer[NI];
__device__ float g_inv2s[NI];
__device__ float g_part[NI * 256];
__device__ float g_self[NI];
__device__ float g_brown[NI];
__device__ float g_ht[NI];
__device__ __half g_wt_h[PROJD * HIDD];          // W^T fp16 (single rounding)
__device__ int g_bucket_cnt[TT];
__device__ int g_bitems[TT * NI];

__device__ __forceinline__ float warp_sum(float v) {
    #pragma unroll
    for (int o = 16; o > 0; o >>= 1) v += __shfl_xor_sync(0xffffffffu, v, o);
    return v;
}

__device__ __forceinline__ uint32_t smem_u32(const void* p) {
    uint32_t a;
    asm("{ .reg .u64 t; cvta.to.shared.u64 t, %1; cvt.u32.u64 %0, t; }" : "=r"(a) : "l"(p));
    return a;
}
__device__ __forceinline__ void cp16(uint32_t dst, const void* src) {
    asm volatile("cp.async.cg.shared.global [%0], [%1], 16;" :: "r"(dst), "l"(src));
}
#define CP_COMMIT() asm volatile("cp.async.commit_group;" ::: "memory")
#define CP_WAIT0()  asm volatile("cp.async.wait_group 0;" ::: "memory")
#define CP_WAIT1()  asm volatile("cp.async.wait_group 1;" ::: "memory")

// reconstruct 4 floats from fp16 hi/lo arrays at index idx (8B aligned)
__device__ __forceinline__ void ld_rec4(const __half* __restrict__ h,
                                        const __half* __restrict__ l,
                                        size_t idx, float* out) {
    __half2 h0 = *(const __half2*)&h[idx];
    __half2 h1 = *(const __half2*)&h[idx + 2];
    __half2 l0 = *(const __half2*)&l[idx];
    __half2 l1 = *(const __half2*)&l[idx + 2];
    out[0] = __half2float(h0.x) + __half2float(l0.x);
    out[1] = __half2float(h0.y) + __half2float(l0.y);
    out[2] = __half2float(h1.x) + __half2float(l1.x);
    out[3] = __half2float(h1.y) + __half2float(l1.y);
}

// sorted-desc top-5 insert
__device__ __forceinline__ void ins5(float* t5, float v) {
    if (v > t5[4]) {
        if (v > t5[0])      { t5[4]=t5[3]; t5[3]=t5[2]; t5[2]=t5[1]; t5[1]=t5[0]; t5[0]=v; }
        else if (v > t5[1]) { t5[4]=t5[3]; t5[3]=t5[2]; t5[2]=t5[1]; t5[1]=v; }
        else if (v > t5[2]) { t5[4]=t5[3]; t5[3]=t5[2]; t5[2]=v; }
        else if (v > t5[3]) { t5[4]=t5[3]; t5[3]=v; }
        else                { t5[4]=v; }
    }
}

// ============ Kernel 0: W -> W^T fp16 ============
__global__ void __launch_bounds__(256) convert_w_kernel(const float* __restrict__ W)
{
    if (blockIdx.x == 0 && threadIdx.x < TT) g_bucket_cnt[threadIdx.x] = 0;
    int k = blockIdx.x;
    int n = threadIdx.x;
    g_wt_h[n * HIDD + k] = __float2half(W[k * PROJD + n]);
}

// ============ Kernel 1: fp16 2-product wmma projection (64M x 256N per CTA, 2 CTA/SM) ============
#define KC   64
#define LDA  72
#define LDB  72
#define STG_LD 260

#define OFF_BIAS  0
#define OFF_U     1024
#define OFF_A_HI  (OFF_U)
#define OFF_A_LO  (OFF_A_HI + 64 * LDA * 2)
#define OFF_B_H   (OFF_A_LO + 64 * LDA * 2)
#define TILES_END (OFF_B_H + 256 * LDB * 2)
#define STG_END   (OFF_U + 64 * STG_LD * 4)
#define PROJ_SMEM (STG_END > TILES_END ? STG_END : TILES_END)

__global__ void __launch_bounds__(256, 2) proj_mma_kernel(
    const float* __restrict__ fe, const float* __restrict__ ofe,
    const float* __restrict__ bias)
{
    extern __shared__ char smem_raw[];
    uint32_t sb = smem_u32(smem_raw);
    float* bias_s = (float*)(smem_raw + OFF_BIAS);
    __half* Ah = (__half*)(smem_raw + OFF_A_HI);
    __half* Al = (__half*)(smem_raw + OFF_A_LO);
    __half* Bh = (__half*)(smem_raw + OFF_B_H);
    float* stage = (float*)(smem_raw + OFF_U);

    int tid  = threadIdx.x;
    int wid  = tid >> 5;
    int lane = tid & 31;

    int b = blockIdx.x;
    const float* A = (b < 400) ? fe : ofe;
    int base = (b < 400) ? 0 : NI;
    int m0   = (b % 400) * 64;

    bias_s[tid] = bias[tid];

    int wm = wid >> 2;
    int wn = wid & 3;

    wmma::fragment<wmma::accumulator, 16, 16, 16, float> acc[2][4];
    #pragma unroll
    for (int mt = 0; mt < 2; mt++)
        #pragma unroll
        for (int nt = 0; nt < 4; nt++)
            wmma::fill_fragment(acc[mt][nt], 0.0f);

    for (int c = 0; c < 4; c++) {
        int k0 = c * KC;
        __syncthreads();
        #pragma unroll
        for (int it = 0; it < 8; it++) {
            int flat = it * 256 + tid;
            int n = flat >> 3;
            int u = flat & 7;
            cp16(sb + OFF_B_H + n * (LDB * 2) + u * 16, &g_wt_h[(size_t)n * HIDD + k0 + u * 8]);
        }
        CP_COMMIT();
        #pragma unroll
        for (int it = 0; it < 4; it++) {
            int flat = it * 256 + tid;
            int row  = flat >> 4;
            int j    = flat & 15;
            float4 v = *(const float4*)&A[(size_t)(m0 + row) * HIDD + k0 + j * 4];
            __half h0 = __float2half(v.x);
            __half h1 = __float2half(v.y);
            __half h2 = __float2half(v.z);
            __half h3 = __float2half(v.w);
            __half l0 = __float2half(v.x - __half2float(h0));
            __half l1 = __float2half(v.y - __half2float(h1));
            __half l2 = __float2half(v.z - __half2float(h2));
            __half l3 = __float2half(v.w - __half2float(h3));
            int o = row * LDA + j * 4;
            *(__half2*)&Ah[o]     = __half2{h0, h1};
            *(__half2*)&Ah[o + 2] = __half2{h2, h3};
            *(__half2*)&Al[o]     = __half2{l0, l1};
            *(__half2*)&Al[o + 2] = __half2{l2, l3};
        }
        CP_WAIT0();
        __syncthreads();

        #pragma unroll
        for (int kt = 0; kt < KC / 16; kt++) {
            wmma::fragment<wmma::matrix_a, 16, 16, 16, __half, wmma::row_major> ah[2], al[2];
            #pragma unroll
            for (int mt = 0; mt < 2; mt++) {
                int row0 = wm * 32 + mt * 16;
                wmma::load_matrix_sync(ah[mt], Ah + row0 * LDA + kt * 16, LDA);
                wmma::load_matrix_sync(al[mt], Al + row0 * LDA + kt * 16, LDA);
            }
            #pragma unroll
            for (int nt = 0; nt < 4; nt++) {
                int n0 = wn * 64 + nt * 16;
                wmma::fragment<wmma::matrix_b, 16, 16, 16, __half, wmma::col_major> bh;
                wmma::load_matrix_sync(bh, Bh + n0 * LDB + kt * 16, LDB);
                #pragma unroll
                for (int mt = 0; mt < 2; mt++) {
                    wmma::mma_sync(acc[mt][nt], ah[mt], bh, acc[mt][nt]);
                    wmma::mma_sync(acc[mt][nt], al[mt], bh, acc[mt][nt]);
                }
            }
        }
    }

    __syncthreads();
    #pragma unroll
    for (int mt = 0; mt < 2; mt++) {
        int row0 = wm * 32 + mt * 16;
        #pragma unroll
        for (int nt = 0; nt < 4; nt++) {
            int n0 = wn * 64 + nt * 16;
            wmma::store_matrix_sync(stage + row0 * STG_LD + n0, acc[mt][nt],
                                    STG_LD, wmma::mem_row_major);
        }
    }
    __syncthreads();

    for (int rr = 0; rr < 8; rr++) {
        int r = wid * 8 + rr;
        float v[8];
        float ss = 0.0f;
        #pragma unroll
        for (int u = 0; u < 8; u++) {
            int cidx = lane + 32 * u;
            float x = stage[r * STG_LD + cidx] + bias_s[cidx];
            v[u] = x;
            ss += x * x;
        }
        ss = warp_sum(ss);
        float inv = rsqrtf(ss);
        int m = m0 + r;
        int q = m % QQ;
        int t = (m / QQ) % TT;
        int bs = m / (QQ * TT);
        int orow = (base + bs * QQ + q) * TT + t;
        #pragma unroll
        for (int u = 0; u < 8; u++) {
            float x = v[u] * inv;
            __half h = __float2half(x);
            size_t o = (size_t)orow * PROJD + lane + 32 * u;
            g_neg_h[o] = h;
            g_neg_l[o] = __float2half(x - __half2float(h));
        }
        if (lane == 0) g_nsq[orow] = ss * inv * inv;
    }
}

// ============ Kernel 2: bridge prep + fused head-tail + bucket push ============
__global__ void __launch_bounds__(256) bridge_prep_kernel(const int* __restrict__ bridge)
{
    int warp = threadIdx.x >> 5;
    int lane = threadIdx.x & 31;
    int i = blockIdx.x * 8 + warp;
    int bh = bridge[i * 3 + 0];
    int bp = bridge[i * 3 + 1];
    int bt = bridge[i * 3 + 2];
    float bhf = (float)bh, bpf = (float)bp, btf = (float)bt;
    float alpha = (bpf - bhf) / (btf - bhf);
    float sigma = alpha * (btf - bpf);
    float inv2s = 1.0f / (2.0f * sigma * sigma);

    size_t r0 = (size_t)(i * TT + bh) * PROJD;
    size_t r1 = (size_t)(i * TT + bp) * PROJD;
    size_t r2 = (size_t)(i * TT + bt) * PROJD;
    size_t rh = (size_t)(i * TT + 0) * PROJD;
    size_t rt = (size_t)(i * TT + (TT - 1)) * PROJD;
    float oma = 1.0f - alpha;
    float xs = 0.0f, as = 0.0f, ht = 0.0f;
    #pragma unroll
    for (int h = 0; h < 2; h++) {
        int c = h * 128 + lane * 4;
        float g0[4], g1[4], g2[4], gh[4], gt[4];
        ld_rec4(g_neg_h, g_neg_l, r0 + c, g0);
        ld_rec4(g_neg_h, g_neg_l, r1 + c, g1);
        ld_rec4(g_neg_h, g_neg_l, r2 + c, g2);
        ld_rec4(g_neg_h, g_neg_l, rh + c, gh);
        ld_rec4(g_neg_h, g_neg_l, rt + c, gt);
        #pragma unroll
        for (int e = 0; e < 4; e++) {
            float aa = oma * g0[e] + alpha * g2[e];
            float x  = g1[e] - oma * g0[e] - alpha * g2[e];
            xs += x * x;
            as += aa * aa;
            ht += gh[e] * gt[e];
            g_a_h[(size_t)i * PROJD + c + e] = __float2half(aa);
        }
    }
    xs = warp_sum(xs);
    as = warp_sum(as);
    ht = warp_sum(ht);
    if (lane == 0) {
        g_inv2s[i] = inv2s;
        g_asq[i]   = as;
        g_numer[i] = expf(-xs * inv2s);
        float z = 0.3f - ht;
        g_ht[i] = log1pf(expf(z));
        int pos = atomicAdd(&g_bucket_cnt[bp], 1);
        g_bitems[bp * NI + pos] = i;
    }
}

// ============ Kernel 3: dist GEMM — fp16 single-product, 64i x 64j, 3 CTAs/SM ============
// cross ~= Ah*Bh  (both lo terms dropped)
#define DKC   64
#define DLD3  72
#define DSTG3 72
#define DS_AH   0
#define DS_BH   9216
#define DS_SZ   18432
#define D3_IDX  (2 * DS_SZ)                 // 36864
#define D3_NSQ  (D3_IDX + 64 * 4)
#define DIST_SMEM (D3_NSQ + 64 * 4 + 16)    // ~37.4 KB

__global__ void __launch_bounds__(256, 3) dist_mma_kernel()
{
    extern __shared__ char smem_raw[];
    uint32_t sbase = smem_u32(smem_raw);
    float* stage = (float*)(smem_raw);
    int* sitems = (int*)(smem_raw + D3_IDX);
    float* snsq = (float*)(smem_raw + D3_NSQ);

    int cidx = blockIdx.y;
    int t = -1, off = 0;
    {
        int acc_c = 0;
        #pragma unroll
        for (int tt2 = 0; tt2 < TT; tt2++) {
            int nch = (g_bucket_cnt[tt2] + 63) >> 6;
            if (t < 0 && cidx < acc_c + nch) { t = tt2; off = (cidx - acc_c) * 64; }
            acc_c += nch;
        }
    }
    if (t < 0) return;
    int cc = min(64, g_bucket_cnt[t] - off);
    int jblock = blockIdx.x;
    int j0 = jblock * 64;

    int tid = threadIdx.x;
    int wid = tid >> 5;
    int wm = wid >> 2;
    int wn = wid & 3;

    if (tid < 64) {
        sitems[tid] = g_bitems[t * NI + off + ((tid < cc) ? tid : 0)];
        snsq[tid]   = g_nsq[(j0 + tid) * TT + t];
    }
    __syncthreads();

    int l_r0 = tid >> 3;
    int l_k  = tid & 7;
    int ai0 = sitems[l_r0];
    int ai1 = sitems[32 + l_r0];

    wmma::fragment<wmma::accumulator, 16, 16, 16, float> acc[2];
    wmma::fill_fragment(acc[0], 0.0f);
    wmma::fill_fragment(acc[1], 0.0f);

    auto prefetch = [&](int c, int buf) {
        int kbase = c * DKC;
        uint32_t st = sbase + buf * DS_SZ;
        uint32_t d0 = st + l_r0 * 144 + l_k * 16;
        uint32_t d1 = st + (32 + l_r0) * 144 + l_k * 16;
        size_t sa0 = (size_t)ai0 * PROJD + kbase + l_k * 8;
        size_t sa1 = (size_t)ai1 * PROJD + kbase + l_k * 8;
        cp16(d0 + DS_AH, &g_a_h[sa0]);
        cp16(d1 + DS_AH, &g_a_h[sa1]);
        size_t sb0 = (size_t)((j0 + l_r0) * TT + t) * PROJD + kbase + l_k * 8;
        size_t sb1 = (size_t)((j0 + 32 + l_r0) * TT + t) * PROJD + kbase + l_k * 8;
        cp16(d0 + DS_BH, &g_neg_h[sb0]);
        cp16(d1 + DS_BH, &g_neg_h[sb1]);
    };

    prefetch(0, 0);
    CP_COMMIT();

    #pragma unroll
    for (int c = 0; c < 4; c++) {
        int buf = c & 1;
        if (c < 3) { prefetch(c + 1, (c + 1) & 1); CP_COMMIT(); CP_WAIT1(); }
        else       { CP_WAIT0(); }
        __syncthreads();

        const __half* Ah = (const __half*)(smem_raw + buf * DS_SZ + DS_AH);
        const __half* Bh = (const __half*)(smem_raw + buf * DS_SZ + DS_BH);

        #pragma unroll
        for (int kt = 0; kt < DKC / 16; kt++) {
            wmma::fragment<wmma::matrix_a, 16, 16, 16, __half, wmma::row_major> ah[2];
            #pragma unroll
            for (int mt = 0; mt < 2; mt++) {
                int row0 = wm * 32 + mt * 16;
                wmma::load_matrix_sync(ah[mt], Ah + row0 * DLD3 + kt * 16, DLD3);
            }
            wmma::fragment<wmma::matrix_b, 16, 16, 16, __half, wmma::col_major> bh;
            wmma::load_matrix_sync(bh, Bh + (wn * 16) * DLD3 + kt * 16, DLD3);
            #pragma unroll
            for (int mt = 0; mt < 2; mt++)
                wmma::mma_sync(acc[mt], ah[mt], bh, acc[mt]);
        }
        __syncthreads();
    }

    #pragma unroll
    for (int mt = 0; mt < 2; mt++)
        wmma::store_matrix_sync(stage + (wm * 32 + mt * 16) * DSTG3 + wn * 16,
                                acc[mt], DSTG3, wmma::mem_row_major);
    __syncthreads();

    int r  = tid >> 2;
    int c0 = (tid & 3) * 16;
    int i = sitems[r];
    bool valid = (r < cc);
    float asqi = g_asq[i];
    float is2  = g_inv2s[i];
    float t5[5] = {-1e30f, -1e30f, -1e30f, -1e30f, -1e30f};
    #pragma unroll
    for (int u = 0; u < 16; u++) {
        int j = j0 + c0 + u;
        float cross = stage[r * DSTG3 + c0 + u];
        float d = -(snsq[c0 + u] - 2.0f * cross + asqi) * is2;
        if (j == i) { if (valid) g_self[i] = d; d = -10000.0f; }
        ins5(t5, d);
    }
    #pragma unroll
    for (int o2 = 1; o2 <= 2; o2 <<= 1) {
        float b0 = __shfl_xor_sync(0xffffffffu, t5[0], o2);
        float b1 = __shfl_xor_sync(0xffffffffu, t5[1], o2);
        float b2 = __shfl_xor_sync(0xffffffffu, t5[2], o2);
        float b3 = __shfl_xor_sync(0xffffffffu, t5[3], o2);
        float b4 = __shfl_xor_sync(0xffffffffu, t5[4], o2);
        ins5(t5, b0); ins5(t5, b1); ins5(t5, b2); ins5(t5, b3); ins5(t5, b4);
    }
    if (valid && (tid & 3) == 0) {
        float* dst = &g_part[(size_t)i * 256 + jblock * 5];
        dst[0] = t5[0]; dst[1] = t5[1]; dst[2] = t5[2]; dst[3] = t5[3]; dst[4] = t5[4];
    }
}

// ============ Kernel 4: warp-per-row merge of partial top-5s ============
__global__ void __launch_bounds__(256) topk_kernel()
{
    int wid  = threadIdx.x >> 5;
    int lane = threadIdx.x & 31;
    int i = blockIdx.x * 8 + wid;
    const float* part = &g_part[(size_t)i * 256];

    float t5[5] = {-1e30f, -1e30f, -1e30f, -1e30f, -1e30f};
    for (int k = lane; k < NJB * 5; k += 32) ins5(t5, part[k]);
    #pragma unroll
    for (int off = 16; off > 0; off >>= 1) {
        float b0 = __shfl_xor_sync(0xffffffffu, t5[0], off);
        float b1 = __shfl_xor_sync(0xffffffffu, t5[1], off);
        float b2 = __shfl_xor_sync(0xffffffffu, t5[2], off);
        float b3 = __shfl_xor_sync(0xffffffffu, t5[3], off);
        float b4 = __shfl_xor_sync(0xffffffffu, t5[4], off);
        ins5(t5, b0); ins5(t5, b1); ins5(t5, b2); ins5(t5, b3); ins5(t5, b4);
    }
    if (lane == 0) {
        float deno = expf(g_self[i]);
        #pragma unroll
        for (int k = 0; k < 5; k++) deno += expf(t5[k]);
        g_brown[i] = g_numer[i] / deno;
    }
}

// ============ Kernel 5: deterministic final reduction ============
__global__ void __launch_bounds__(256) final_kernel(float* __restrict__ out)
{
    __shared__ float sb[256], sh[256];
    int tid = threadIdx.x;
    float b = 0.0f, h = 0.0f;
    for (int i = tid; i < NI; i += 256) { b += g_brown[i]; h += g_ht[i]; }
    sb[tid] = b; sh[tid] = h;
    __syncthreads();
    for (int s = 128; s > 0; s >>= 1) {
        if (tid < s) { sb[tid] += sb[tid + s]; sh[tid] += sh[tid + s]; }
        __syncthreads();
    }
    if (tid == 0) {
        out[0] = sb[0] / (float)NI;
        out[1] = sh[0] / (float)NI;
    }
}

// ==================== launch ====================
extern "C" void kernel_launch(void* const* d_in, const int* in_sizes, int n_in,
                              void* d_out, int out_size)
{
    const float* fe     = (const float*)d_in[0];
    const float* ofe    = (const float*)d_in[1];
    const float* W      = (const float*)d_in[2];
    const float* bias   = (const float*)d_in[3];
    const int*   bridge = (const int*)d_in[4];
    float* out = (float*)d_out;

    cudaFuncSetAttribute(proj_mma_kernel, cudaFuncAttributeMaxDynamicSharedMemorySize, PROJ_SMEM);
    cudaFuncSetAttribute(dist_mma_kernel, cudaFuncAttributeMaxDynamicSharedMemorySize, DIST_SMEM);

    convert_w_kernel<<<HIDD, PROJD>>>(W);
    proj_mma_kernel<<<800, 256, PROJ_SMEM>>>(fe, ofe, bias);

    bridge_prep_kernel<<<NI / 8, 256>>>(bridge);
    dist_mma_kernel<<<dim3(NJB, MAXC), 256, DIST_SMEM>>>();
    topk_kernel<<<NI / 8, 256>>>();
    final_kernel<<<1, 256>>>(out);
}

// round 17
// speedup vs baseline: 1.7938x; 1.1174x over previous
#include <cstdint>
#include <stdint.h>
#include <cuda_runtime.h>
#include <cuda_bf16.h>
#include <cuda_fp16.h>
#include <mma.h>
#include <math.h>

using namespace nvcuda;

#define BSZ   16
#define TT    16
#define QQ    100
#define HIDD  256
#define PROJD 256
#define NI    1600    // BS*Q
#define MROWS 25600   // BS*T*Q
#define NNEG  3200
#define NJB   (NNEG / 64)      // 50 j-blocks of 64
#define MAXC  (NI / 64 + TT)   // 41 chunk slots upper bound

// -------- scratch (device globals; no allocation allowed) --------
__device__ __half g_neg_h[NNEG * TT * PROJD];
__device__ __half g_neg_l[NNEG * TT * PROJD];
__device__ float g_nsq[NNEG * TT];
__device__ __half g_a_h[NI * PROJD];
__device__ float g_asq[NI];
__device__ float g_numer[NI];
__device__ float g_inv2s[NI];
__device__ float g_part[NI * 256];
__device__ float g_self[NI];
__device__ float g_brown[NI];
__device__ float g_ht[NI];
__device__ __half g_wt_h[PROJD * HIDD];          // W^T fp16 (single rounding)
__device__ int g_bucket_cnt[TT];
__device__ int g_bitems[TT * NI];

__device__ __forceinline__ float warp_sum(float v) {
    #pragma unroll
    for (int o = 16; o > 0; o >>= 1) v += __shfl_xor_sync(0xffffffffu, v, o);
    return v;
}

__device__ __forceinline__ uint32_t smem_u32(const void* p) {
    uint32_t a;
    asm("{ .reg .u64 t; cvta.to.shared.u64 t, %1; cvt.u32.u64 %0, t; }" : "=r"(a) : "l"(p));
    return a;
}
__device__ __forceinline__ void cp16(uint32_t dst, const void* src) {
    asm volatile("cp.async.cg.shared.global [%0], [%1], 16;" :: "r"(dst), "l"(src));
}
#define CP_COMMIT() asm volatile("cp.async.commit_group;" ::: "memory")
#define CP_WAIT0()  asm volatile("cp.async.wait_group 0;" ::: "memory")
#define CP_WAIT1()  asm volatile("cp.async.wait_group 1;" ::: "memory")

// reconstruct 4 floats from fp16 hi/lo arrays at index idx (8B aligned)
__device__ __forceinline__ void ld_rec4(const __half* __restrict__ h,
                                        const __half* __restrict__ l,
                                        size_t idx, float* out) {
    __half2 h0 = *(const __half2*)&h[idx];
    __half2 h1 = *(const __half2*)&h[idx + 2];
    __half2 l0 = *(const __half2*)&l[idx];
    __half2 l1 = *(const __half2*)&l[idx + 2];
    out[0] = __half2float(h0.x) + __half2float(l0.x);
    out[1] = __half2float(h0.y) + __half2float(l0.y);
    out[2] = __half2float(h1.x) + __half2float(l1.x);
    out[3] = __half2float(h1.y) + __half2float(l1.y);
}

// sorted-desc top-5 insert
__device__ __forceinline__ void ins5(float* t5, float v) {
    if (v > t5[4]) {
        if (v > t5[0])      { t5[4]=t5[3]; t5[3]=t5[2]; t5[2]=t5[1]; t5[1]=t5[0]; t5[0]=v; }
        else if (v > t5[1]) { t5[4]=t5[3]; t5[3]=t5[2]; t5[2]=t5[1]; t5[1]=v; }
        else if (v > t5[2]) { t5[4]=t5[3]; t5[3]=t5[2]; t5[2]=v; }
        else if (v > t5[3]) { t5[4]=t5[3]; t5[3]=v; }
        else                { t5[4]=v; }
    }
}

// ============ Kernel 0: W -> W^T fp16 ============
__global__ void __launch_bounds__(256) convert_w_kernel(const float* __restrict__ W)
{
    if (blockIdx.x == 0 && threadIdx.x < TT) g_bucket_cnt[threadIdx.x] = 0;
    int k = blockIdx.x;
    int n = threadIdx.x;
    g_wt_h[n * HIDD + k] = __float2half(W[k * PROJD + n]);
}

// ============ Kernel 1: fp16 single-product wmma projection (64M x 256N, 2 CTA/SM) ============
// x*W ~= Ah*Wh  (single fp16 rounding on both operands; result stored hi+lo)
#define KC   64
#define LDA  72
#define LDB  72
#define STG_LD 260

#define OFF_BIAS  0
#define OFF_U     1024
#define OFF_A_HI  (OFF_U)
#define OFF_B_H   (OFF_A_HI + 64 * LDA * 2)      // 10240
#define TILES_END (OFF_B_H + 256 * LDB * 2)      // 47104
#define STG_END   (OFF_U + 64 * STG_LD * 4)      // 67584
#define PROJ_SMEM (STG_END > TILES_END ? STG_END : TILES_END)

__global__ void __launch_bounds__(256, 2) proj_mma_kernel(
    const float* __restrict__ fe, const float* __restrict__ ofe,
    const float* __restrict__ bias)
{
    extern __shared__ char smem_raw[];
    uint32_t sb = smem_u32(smem_raw);
    float* bias_s = (float*)(smem_raw + OFF_BIAS);
    __half* Ah = (__half*)(smem_raw + OFF_A_HI);
    __half* Bh = (__half*)(smem_raw + OFF_B_H);
    float* stage = (float*)(smem_raw + OFF_U);

    int tid  = threadIdx.x;
    int wid  = tid >> 5;
    int lane = tid & 31;

    int b = blockIdx.x;
    const float* A = (b < 400) ? fe : ofe;
    int base = (b < 400) ? 0 : NI;
    int m0   = (b % 400) * 64;

    bias_s[tid] = bias[tid];

    int wm = wid >> 2;
    int wn = wid & 3;

    wmma::fragment<wmma::accumulator, 16, 16, 16, float> acc[2][4];
    #pragma unroll
    for (int mt = 0; mt < 2; mt++)
        #pragma unroll
        for (int nt = 0; nt < 4; nt++)
            wmma::fill_fragment(acc[mt][nt], 0.0f);

    for (int c = 0; c < 4; c++) {
        int k0 = c * KC;
        __syncthreads();
        // ---- issue B chunk via cp.async (overlaps A load/convert below) ----
        #pragma unroll
        for (int it = 0; it < 8; it++) {
            int flat = it * 256 + tid;
            int n = flat >> 3;
            int u = flat & 7;
            cp16(sb + OFF_B_H + n * (LDB * 2) + u * 16, &g_wt_h[(size_t)n * HIDD + k0 + u * 8]);
        }
        CP_COMMIT();
        // ---- load & convert A chunk: 64 rows x 64 fp32 -> fp16 ----
        #pragma unroll
        for (int it = 0; it < 4; it++) {
            int flat = it * 256 + tid;
            int row  = flat >> 4;
            int j    = flat & 15;
            float4 v = *(const float4*)&A[(size_t)(m0 + row) * HIDD + k0 + j * 4];
            int o = row * LDA + j * 4;
            *(__half2*)&Ah[o]     = __half2{__float2half(v.x), __float2half(v.y)};
            *(__half2*)&Ah[o + 2] = __half2{__float2half(v.z), __float2half(v.w)};
        }
        CP_WAIT0();
        __syncthreads();

        #pragma unroll
        for (int kt = 0; kt < KC / 16; kt++) {
            wmma::fragment<wmma::matrix_a, 16, 16, 16, __half, wmma::row_major> ah[2];
            #pragma unroll
            for (int mt = 0; mt < 2; mt++) {
                int row0 = wm * 32 + mt * 16;
                wmma::load_matrix_sync(ah[mt], Ah + row0 * LDA + kt * 16, LDA);
            }
            #pragma unroll
            for (int nt = 0; nt < 4; nt++) {
                int n0 = wn * 64 + nt * 16;
                wmma::fragment<wmma::matrix_b, 16, 16, 16, __half, wmma::col_major> bh;
                wmma::load_matrix_sync(bh, Bh + n0 * LDB + kt * 16, LDB);
                #pragma unroll
                for (int mt = 0; mt < 2; mt++)
                    wmma::mma_sync(acc[mt][nt], ah[mt], bh, acc[mt][nt]);
            }
        }
    }

    __syncthreads();
    #pragma unroll
    for (int mt = 0; mt < 2; mt++) {
        int row0 = wm * 32 + mt * 16;
        #pragma unroll
        for (int nt = 0; nt < 4; nt++) {
            int n0 = wn * 64 + nt * 16;
            wmma::store_matrix_sync(stage + row0 * STG_LD + n0, acc[mt][nt],
                                    STG_LD, wmma::mem_row_major);
        }
    }
    __syncthreads();

    for (int rr = 0; rr < 8; rr++) {
        int r = wid * 8 + rr;
        float v[8];
        float ss = 0.0f;
        #pragma unroll
        for (int u = 0; u < 8; u++) {
            int cidx = lane + 32 * u;
            float x = stage[r * STG_LD + cidx] + bias_s[cidx];
            v[u] = x;
            ss += x * x;
        }
        ss = warp_sum(ss);
        float inv = rsqrtf(ss);
        int m = m0 + r;
        int q = m % QQ;
        int t = (m / QQ) % TT;
        int bs = m / (QQ * TT);
        int orow = (base + bs * QQ + q) * TT + t;
        #pragma unroll
        for (int u = 0; u < 8; u++) {
            float x = v[u] * inv;
            __half h = __float2half(x);
            size_t o = (size_t)orow * PROJD + lane + 32 * u;
            g_neg_h[o] = h;
            g_neg_l[o] = __float2half(x - __half2float(h));
        }
        if (lane == 0) g_nsq[orow] = ss * inv * inv;
    }
}

// ============ Kernel 2: bridge prep + fused head-tail + bucket push ============
__global__ void __launch_bounds__(256) bridge_prep_kernel(const int* __restrict__ bridge)
{
    int warp = threadIdx.x >> 5;
    int lane = threadIdx.x & 31;
    int i = blockIdx.x * 8 + warp;
    int bh = bridge[i * 3 + 0];
    int bp = bridge[i * 3 + 1];
    int bt = bridge[i * 3 + 2];
    float bhf = (float)bh, bpf = (float)bp, btf = (float)bt;
    float alpha = (bpf - bhf) / (btf - bhf);
    float sigma = alpha * (btf - bpf);
    float inv2s = 1.0f / (2.0f * sigma * sigma);

    size_t r0 = (size_t)(i * TT + bh) * PROJD;
    size_t r1 = (size_t)(i * TT + bp) * PROJD;
    size_t r2 = (size_t)(i * TT + bt) * PROJD;
    size_t rh = (size_t)(i * TT + 0) * PROJD;
    size_t rt = (size_t)(i * TT + (TT - 1)) * PROJD;
    float oma = 1.0f - alpha;
    float xs = 0.0f, as = 0.0f, ht = 0.0f;
    #pragma unroll
    for (int h = 0; h < 2; h++) {
        int c = h * 128 + lane * 4;
        float g0[4], g1[4], g2[4], gh[4], gt[4];
        ld_rec4(g_neg_h, g_neg_l, r0 + c, g0);
        ld_rec4(g_neg_h, g_neg_l, r1 + c, g1);
        ld_rec4(g_neg_h, g_neg_l, r2 + c, g2);
        ld_rec4(g_neg_h, g_neg_l, rh + c, gh);
        ld_rec4(g_neg_h, g_neg_l, rt + c, gt);
        #pragma unroll
        for (int e = 0; e < 4; e++) {
            float aa = oma * g0[e] + alpha * g2[e];
            float x  = g1[e] - oma * g0[e] - alpha * g2[e];
            xs += x * x;
            as += aa * aa;
            ht += gh[e] * gt[e];
            g_a_h[(size_t)i * PROJD + c + e] = __float2half(aa);
        }
    }
    xs = warp_sum(xs);
    as = warp_sum(as);
    ht = warp_sum(ht);
    if (lane == 0) {
        g_inv2s[i] = inv2s;
        g_asq[i]   = as;
        g_numer[i] = expf(-xs * inv2s);
        float z = 0.3f - ht;
        g_ht[i] = log1pf(expf(z));
        int pos = atomicAdd(&g_bucket_cnt[bp], 1);
        g_bitems[bp * NI + pos] = i;
    }
}

// ============ Kernel 3: dist GEMM — fp16 single-product, 64i x 64j, 3 CTAs/SM ============
#define DKC   64
#define DLD3  72
#define DSTG3 72
#define DS_AH   0
#define DS_BH   9216
#define DS_SZ   18432
#define D3_IDX  (2 * DS_SZ)                 // 36864
#define D3_NSQ  (D3_IDX + 64 * 4)
#define D3_TOFF (D3_NSQ + 64 * 4)
#define DIST_SMEM (D3_TOFF + 16)

__global__ void __launch_bounds__(256, 3) dist_mma_kernel()
{
    extern __shared__ char smem_raw[];
    uint32_t sbase = smem_u32(smem_raw);
    float* stage = (float*)(smem_raw);
    int* sitems = (int*)(smem_raw + D3_IDX);
    float* snsq = (float*)(smem_raw + D3_NSQ);
    int* stoff = (int*)(smem_raw + D3_TOFF);

    int tid = threadIdx.x;

    // ---- thread 0 maps blockIdx.y -> (t, off); broadcast via smem ----
    if (tid == 0) {
        int cidx = blockIdx.y;
        int t2 = -1, off2 = 0;
        int acc_c = 0;
        #pragma unroll
        for (int tt2 = 0; tt2 < TT; tt2++) {
            int nch = (g_bucket_cnt[tt2] + 63) >> 6;
            if (t2 < 0 && cidx < acc_c + nch) { t2 = tt2; off2 = (cidx - acc_c) * 64; }
            acc_c += nch;
        }
        stoff[0] = t2;
        stoff[1] = off2;
    }
    __syncthreads();
    int t = stoff[0];
    int off = stoff[1];
    if (t < 0) return;
    int cc = min(64, g_bucket_cnt[t] - off);
    int jblock = blockIdx.x;
    int j0 = jblock * 64;

    int wid = tid >> 5;
    int wm = wid >> 2;
    int wn = wid & 3;

    if (tid < 64) {
        sitems[tid] = g_bitems[t * NI + off + ((tid < cc) ? tid : 0)];
        snsq[tid]   = g_nsq[(j0 + tid) * TT + t];
    }
    __syncthreads();

    int l_r0 = tid >> 3;
    int l_k  = tid & 7;
    int ai0 = sitems[l_r0];
    int ai1 = sitems[32 + l_r0];

    wmma::fragment<wmma::accumulator, 16, 16, 16, float> acc[2];
    wmma::fill_fragment(acc[0], 0.0f);
    wmma::fill_fragment(acc[1], 0.0f);

    auto prefetch = [&](int c, int buf) {
        int kbase = c * DKC;
        uint32_t st = sbase + buf * DS_SZ;
        uint32_t d0 = st + l_r0 * 144 + l_k * 16;
        uint32_t d1 = st + (32 + l_r0) * 144 + l_k * 16;
        size_t sa0 = (size_t)ai0 * PROJD + kbase + l_k * 8;
        size_t sa1 = (size_t)ai1 * PROJD + kbase + l_k * 8;
        cp16(d0 + DS_AH, &g_a_h[sa0]);
        cp16(d1 + DS_AH, &g_a_h[sa1]);
        size_t sb0 = (size_t)((j0 + l_r0) * TT + t) * PROJD + kbase + l_k * 8;
        size_t sb1 = (size_t)((j0 + 32 + l_r0) * TT + t) * PROJD + kbase + l_k * 8;
        cp16(d0 + DS_BH, &g_neg_h[sb0]);
        cp16(d1 + DS_BH, &g_neg_h[sb1]);
    };

    prefetch(0, 0);
    CP_COMMIT();

    #pragma unroll
    for (int c = 0; c < 4; c++) {
        int buf = c & 1;
        if (c < 3) { prefetch(c + 1, (c + 1) & 1); CP_COMMIT(); CP_WAIT1(); }
        else       { CP_WAIT0(); }
        __syncthreads();

        const __half* Ah = (const __half*)(smem_raw + buf * DS_SZ + DS_AH);
        const __half* Bh = (const __half*)(smem_raw + buf * DS_SZ + DS_BH);

        #pragma unroll
        for (int kt = 0; kt < DKC / 16; kt++) {
            wmma::fragment<wmma::matrix_a, 16, 16, 16, __half, wmma::row_major> ah[2];
            #pragma unroll
            for (int mt = 0; mt < 2; mt++) {
                int row0 = wm * 32 + mt * 16;
                wmma::load_matrix_sync(ah[mt], Ah + row0 * DLD3 + kt * 16, DLD3);
            }
            wmma::fragment<wmma::matrix_b, 16, 16, 16, __half, wmma::col_major> bh;
            wmma::load_matrix_sync(bh, Bh + (wn * 16) * DLD3 + kt * 16, DLD3);
            #pragma unroll
            for (int mt = 0; mt < 2; mt++)
                wmma::mma_sync(acc[mt], ah[mt], bh, acc[mt]);
        }
        __syncthreads();
    }

    #pragma unroll
    for (int mt = 0; mt < 2; mt++)
        wmma::store_matrix_sync(stage + (wm * 32 + mt * 16) * DSTG3 + wn * 16,
                                acc[mt], DSTG3, wmma::mem_row_major);
    __syncthreads();

    int r  = tid >> 2;
    int c0 = (tid & 3) * 16;
    int i = sitems[r];
    bool valid = (r < cc);
    float asqi = g_asq[i];
    float is2  = g_inv2s[i];
    float t5[5] = {-1e30f, -1e30f, -1e30f, -1e30f, -1e30f};
    #pragma unroll
    for (int u = 0; u < 16; u++) {
        int j = j0 + c0 + u;
        float cross = stage[r * DSTG3 + c0 + u];
        float d = -(snsq[c0 + u] - 2.0f * cross + asqi) * is2;
        if (j == i) { if (valid) g_self[i] = d; d = -10000.0f; }
        ins5(t5, d);
    }
    #pragma unroll
    for (int o2 = 1; o2 <= 2; o2 <<= 1) {
        float b0 = __shfl_xor_sync(0xffffffffu, t5[0], o2);
        float b1 = __shfl_xor_sync(0xffffffffu, t5[1], o2);
        float b2 = __shfl_xor_sync(0xffffffffu, t5[2], o2);
        float b3 = __shfl_xor_sync(0xffffffffu, t5[3], o2);
        float b4 = __shfl_xor_sync(0xffffffffu, t5[4], o2);
        ins5(t5, b0); ins5(t5, b1); ins5(t5, b2); ins5(t5, b3); ins5(t5, b4);
    }
    if (valid && (tid & 3) == 0) {
        float* dst = &g_part[(size_t)i * 256 + jblock * 5];
        dst[0] = t5[0]; dst[1] = t5[1]; dst[2] = t5[2]; dst[3] = t5[3]; dst[4] = t5[4];
    }
}

// ============ Kernel 4: warp-per-row merge of partial top-5s ============
__global__ void __launch_bounds__(256) topk_kernel()
{
    int wid  = threadIdx.x >> 5;
    int lane = threadIdx.x & 31;
    int i = blockIdx.x * 8 + wid;
    const float* part = &g_part[(size_t)i * 256];

    float t5[5] = {-1e30f, -1e30f, -1e30f, -1e30f, -1e30f};
    for (int k = lane; k < NJB * 5; k += 32) ins5(t5, part[k]);
    #pragma unroll
    for (int off = 16; off > 0; off >>= 1) {
        float b0 = __shfl_xor_sync(0xffffffffu, t5[0], off);
        float b1 = __shfl_xor_sync(0xffffffffu, t5[1], off);
        float b2 = __shfl_xor_sync(0xffffffffu, t5[2], off);
        float b3 = __shfl_xor_sync(0xffffffffu, t5[3], off);
        float b4 = __shfl_xor_sync(0xffffffffu, t5[4], off);
        ins5(t5, b0); ins5(t5, b1); ins5(t5, b2); ins5(t5, b3); ins5(t5, b4);
    }
    if (lane == 0) {
        float deno = expf(g_self[i]);
        #pragma unroll
        for (int k = 0; k < 5; k++) deno += expf(t5[k]);
        g_brown[i] = g_numer[i] / deno;
    }
}

// ============ Kernel 5: deterministic final reduction ============
__global__ void __launch_bounds__(256) final_kernel(float* __restrict__ out)
{
    __shared__ float sb[256], sh[256];
    int tid = threadIdx.x;
    float b = 0.0f, h = 0.0f;
    for (int i = tid; i < NI; i += 256) { b += g_brown[i]; h += g_ht[i]; }
    sb[tid] = b; sh[tid] = h;
    __syncthreads();
    for (int s = 128; s > 0; s >>= 1) {
        if (tid < s) { sb[tid] += sb[tid + s]; sh[tid] += sh[tid + s]; }
        __syncthreads();
    }
    if (tid == 0) {
        out[0] = sb[0] / (float)NI;
        out[1] = sh[0] / (float)NI;
    }
}

// ==================== launch ====================
extern "C" void kernel_launch(void* const* d_in, const int* in_sizes, int n_in,
                              void* d_out, int out_size)
{
    const float* fe     = (const float*)d_in[0];
    const float* ofe    = (const float*)d_in[1];
    const float* W      = (const float*)d_in[2];
    const float* bias   = (const float*)d_in[3];
    const int*   bridge = (const int*)d_in[4];
    float* out = (float*)d_out;

    cudaFuncSetAttribute(proj_mma_kernel, cudaFuncAttributeMaxDynamicSharedMemorySize, PROJ_SMEM);
    cudaFuncSetAttribute(dist_mma_kernel, cudaFuncAttributeMaxDynamicSharedMemorySize, DIST_SMEM);

    convert_w_kernel<<<HIDD, PROJD>>>(W);
    proj_mma_kernel<<<800, 256, PROJ_SMEM>>>(fe, ofe, bias);

    bridge_prep_kernel<<<NI / 8, 256>>>(bridge);
    dist_mma_kernel<<<dim3(NJB, MAXC), 256, DIST_SMEM>>>();
    topk_kernel<<<NI / 8, 256>>>();
    final_kernel<<<1, 256>>>(out);
}